// round 9
// baseline (speedup 1.0000x reference)
#include <cuda_runtime.h>
#include <cuda_fp16.h>
#include <cuda_fp8.h>
#include <math.h>
#include <stdint.h>

#define NN 100000
#define NC 64
#define NE 3200000
#define NB 400          // blocks for node-elementwise kernels (256 thr)
#define NCH 98          // ceil(NN/1024) scan chunks

// ---------------- scratch (static __device__ — no allocations allowed) ------
__device__ float   g_seed  [(size_t)NN * NC];
__device__ uint8_t g_seed_q[(size_t)NN * NC];     // e4m3
__device__ float   g_propA [(size_t)NN * NC];
__device__ float   g_propB [(size_t)NN * NC];
__device__ uint8_t g_propAq[(size_t)NN * NC];     // e4m3
__device__ uint8_t g_propBq[(size_t)NN * NC];     // e4m3
__device__ float   g_bctx  [(size_t)NN * NC];
__device__ float   g_mass[NN], g_ent[NN];
__device__ float   g_sgate[NN], g_rgate[NN], g_anchor[NN], g_selb[NN], g_den[NN];
__device__ int     g_hist[NN];
__device__ int     g_off[NN + 1];
__device__ int     g_cur[NN];
__device__ int2    g_edge[NE];                    // {src, half2(w, w*sgate[src])}
__device__ int     g_csum[NCH], g_cbase[NCH];
__device__ float   g_pmass[NB], g_pclust[NB];
__device__ float   g_scal[4];                     // 2: conf_sum, 3: graph_scale
__device__ float   g_gp[NC];

// ---------------- helpers ---------------------------------------------------
__device__ __forceinline__ float wsum(float v) {
    #pragma unroll
    for (int o = 16; o; o >>= 1) v += __shfl_xor_sync(0xffffffffu, v, o);
    return v;
}
__device__ __forceinline__ void wtop2(float& m1, float& m2) {
    #pragma unroll
    for (int o = 16; o; o >>= 1) {
        float o1 = __shfl_xor_sync(0xffffffffu, m1, o);
        float o2 = __shfl_xor_sync(0xffffffffu, m2, o);
        float hi = fmaxf(m1, o1);
        float lo = fmaxf(fminf(m1, o1), fmaxf(m2, o2));
        m1 = hi; m2 = lo;
    }
}
__device__ __forceinline__ float clamp01(float x) { return fminf(fmaxf(x, 0.f), 1.f); }
__device__ __forceinline__ float sigmoidf(float x) { return 1.f / (1.f + expf(-x)); }

// 4 × e4m3 (packed u32, ch0 = low byte) -> 4 floats  (cuda_fp8.h intrinsics)
__device__ __forceinline__ float4 fp8x4_to_float4(uint32_t v) {
    __nv_fp8x2_storage_t lo = (__nv_fp8x2_storage_t)(v & 0xffffu);
    __nv_fp8x2_storage_t hi = (__nv_fp8x2_storage_t)(v >> 16);
    __half2_raw h01 = __nv_cvt_fp8x2_to_halfraw2(lo, __NV_E4M3);
    __half2_raw h23 = __nv_cvt_fp8x2_to_halfraw2(hi, __NV_E4M3);
    float2 f01 = __half22float2(*reinterpret_cast<__half2*>(&h01));
    float2 f23 = __half22float2(*reinterpret_cast<__half2*>(&h23));
    return make_float4(f01.x, f01.y, f23.x, f23.y);
}
// 4 floats -> packed 4 × e4m3 (c0 in lowest byte)
__device__ __forceinline__ uint32_t float4_to_fp8x4(float c0, float c1, float c2, float c3) {
    __nv_fp8x2_storage_t lo =
        __nv_cvt_float2_to_fp8x2(make_float2(c0, c1), __NV_SATFINITE, __NV_E4M3);
    __nv_fp8x2_storage_t hi =
        __nv_cvt_float2_to_fp8x2(make_float2(c2, c3), __NV_SATFINITE, __NV_E4M3);
    return (uint32_t)lo | ((uint32_t)hi << 16);
}
__device__ __forceinline__ unsigned short float2_to_fp8x2(float c0, float c1) {
    return (unsigned short)
        __nv_cvt_float2_to_fp8x2(make_float2(c0, c1), __NV_SATFINITE, __NV_E4M3);
}
// running top2 insert
__device__ __forceinline__ void top2_ins(float v, float& m1, float& m2) {
    float nm1 = fmaxf(m1, v);
    m2 = fmaxf(m2, fminf(m1, v));
    m1 = nm1;
}

// ---------------- kernels ---------------------------------------------------
// seed = relu(logits); mass/entropy; partial sums; zero hist/gp/scal
__global__ void __launch_bounds__(256) k_seed(const float* __restrict__ logits,
                                              const float* __restrict__ sf) {
    __shared__ float sm_mass[8], sm_clust[8];
    int t = blockIdx.x * blockDim.x + threadIdx.x;
    if (t < NN) g_hist[t] = 0;
    if (t < NC) g_gp[t] = 0.f;
    if (t < 4)  g_scal[t] = 0.f;
    int warp = t >> 5;
    int lane = threadIdx.x & 31;
    int wib  = threadIdx.x >> 5;
    int nw   = (gridDim.x * blockDim.x) >> 5;
    float lmass = 0.f, lclust = 0.f;
    for (int n = warp; n < NN; n += nw) {
        float2 lg = reinterpret_cast<const float2*>(logits + (size_t)n * NC)[lane];
        float2 s  = make_float2(fmaxf(lg.x, 0.f), fmaxf(lg.y, 0.f));
        reinterpret_cast<float2*>(g_seed + (size_t)n * NC)[lane] = s;
        reinterpret_cast<unsigned short*>(g_seed_q + (size_t)n * NC)[lane] =
            float2_to_fp8x2(s.x, s.y);
        float mass = wsum(s.x + s.y);
        float inv  = 1.f / (mass + 1e-8f);
        float nx = s.x * inv, ny = s.y * inv;
        float e   = -(nx * logf(nx + 1e-8f) + ny * logf(ny + 1e-8f));
        float ent = wsum(e);
        if (lane == 0) {
            g_mass[n] = mass; g_ent[n] = ent;
            lmass += mass; lclust += sf[2 * n + 1];
        }
    }
    if (lane == 0) { sm_mass[wib] = lmass; sm_clust[wib] = lclust; }
    __syncthreads();
    if (threadIdx.x == 0) {
        float m = 0.f, c = 0.f;
        #pragma unroll
        for (int i = 0; i < 8; i++) { m += sm_mass[i]; c += sm_clust[i]; }
        g_pmass[blockIdx.x] = m; g_pclust[blockIdx.x] = c;
    }
}

// confidence, gates, anchor, selective-base; global prior numerator & conf sum
__global__ void __launch_bounds__(256) k_conf(const float* __restrict__ sf) {
    __shared__ float sm[256];
    float acc = 0.f;
    for (int i = threadIdx.x; i < NB; i += 256) acc += g_pmass[i];
    sm[threadIdx.x] = acc;
    __syncthreads();
    for (int o = 128; o; o >>= 1) {
        if (threadIdx.x < o) sm[threadIdx.x] += sm[threadIdx.x + o];
        __syncthreads();
    }
    float scale = fmaxf(sm[0] * (1.f / (float)NN), 1e-8f);
    __syncthreads();

    int warp = (blockIdx.x * blockDim.x + threadIdx.x) >> 5;
    int lane = threadIdx.x & 31;
    int nw   = (gridDim.x * blockDim.x) >> 5;
    const float invlog = 1.f / logf(64.f);
    float2 gpacc = make_float2(0.f, 0.f);
    float lconf = 0.f;
    for (int n = warp; n < NN; n += nw) {
        float mass = g_mass[n], ent = g_ent[n];
        float cert = 1.f - ent * invlog;
        float mag  = tanhf(mass / scale);
        float conf = clamp01(0.5f * cert + 0.5f * mag);
        float2 s = reinterpret_cast<const float2*>(g_seed + (size_t)n * NC)[lane];
        gpacc.x += conf * s.x;  gpacc.y += conf * s.y;
        if (lane == 0) {
            lconf += conf;
            g_sgate[n]  = sigmoidf(8.f * (conf - 0.55f));
            g_rgate[n]  = sigmoidf(8.f * (0.5f - conf));
            g_anchor[n] = fminf(fmaxf(0.6f + 0.2f * conf, 0.f), 0.995f);
            float ld = clamp01(1.f - sf[2 * n + 0]);
            float lc = clamp01(1.f - sf[2 * n + 1]);
            g_selb[n] = (1.f - conf) + 0.25f * ld + 0.2f * lc;
        }
    }
    atomicAdd(&g_gp[2 * lane + 0], gpacc.x);
    atomicAdd(&g_gp[2 * lane + 1], gpacc.y);
    if (lane == 0) atomicAdd(&g_scal[2], lconf);
}

// histogram of dst + finalize global prior & graph_scale
__global__ void k_hist(const int* __restrict__ dst) {
    if (blockIdx.x == 0 && threadIdx.x == 0) {
        float c = 0.f;
        for (int i = 0; i < NB; i++) c += g_pclust[i];
        g_scal[3] = fminf(fmaxf(1.f - c * (1.f / (float)NN), 0.2f), 1.f);
    }
    if (blockIdx.x == 1 && threadIdx.x < NC) {
        g_gp[threadIdx.x] /= fmaxf(g_scal[2], 1e-8f);
    }
    int e = blockIdx.x * blockDim.x + threadIdx.x;
    int stride = gridDim.x * blockDim.x;
    for (; e < NE; e += stride) atomicAdd(&g_hist[dst[e]], 1);
}

// ---- parallel 3-phase exclusive scan of g_hist -> g_off, g_cur -------------
__global__ void __launch_bounds__(1024) k_scan1() {
    __shared__ int wsums[32];
    int tid = threadIdx.x;
    int lane = tid & 31;
    int i = blockIdx.x * 1024 + tid;
    int v = (i < NN) ? g_hist[i] : 0;
    int x = v;
    #pragma unroll
    for (int o = 1; o < 32; o <<= 1) {
        int t = __shfl_up_sync(0xffffffffu, x, o);
        if (lane >= o) x += t;
    }
    if (lane == 31) wsums[tid >> 5] = x;
    __syncthreads();
    if (tid < 32) {
        int s = wsums[tid];
        #pragma unroll
        for (int o = 1; o < 32; o <<= 1) {
            int t = __shfl_up_sync(0xffffffffu, s, o);
            if (lane >= o) s += t;
        }
        wsums[tid] = s;
    }
    __syncthreads();
    int base = (tid >= 32) ? wsums[(tid >> 5) - 1] : 0;
    int inc = x + base;
    if (i < NN) g_off[i] = inc - v;
    if (tid == 1023) g_csum[blockIdx.x] = inc;
}
__global__ void k_scan2() {
    __shared__ int sh[128];
    int tid = threadIdx.x;
    int v = (tid < NCH) ? g_csum[tid] : 0;
    sh[tid] = v;
    __syncthreads();
    for (int o = 1; o < 128; o <<= 1) {
        int t = (tid >= o) ? sh[tid - o] : 0;
        __syncthreads();
        sh[tid] += t;
        __syncthreads();
    }
    if (tid < NCH) g_cbase[tid] = sh[tid] - v;
}
__global__ void k_scan3() {
    int i = blockIdx.x * blockDim.x + threadIdx.x;
    if (i < NN) {
        int off = g_off[i] + g_cbase[i >> 10];
        g_off[i] = off;
        g_cur[i] = off;
    }
    if (i == 0) g_off[NN] = NE;
}

// scatter into dst-sorted 8B edge records {src, half2(w, w*sgate[src])}
__global__ void k_scat(const int* __restrict__ src, const int* __restrict__ dst,
                       const float* __restrict__ w) {
    int e = blockIdx.x * blockDim.x + threadIdx.x;
    int stride = gridDim.x * blockDim.x;
    for (; e < NE; e += stride) {
        int d = dst[e];
        int s = src[e];
        float wv = w[e];
        float sg = g_sgate[s];
        int pos = atomicAdd(&g_cur[d], 1);
        __half2 hp = __halves2half2(__float2half_rn(wv),
                                    __float2half_rn(wv * sg));
        int2 rec;
        rec.x = s;
        rec.y = *reinterpret_cast<int*>(&hp);
        g_edge[pos] = rec;
    }
}

// ---------------- fused gather-SPMM + epilogue -------------------------------
// Warp per dst node. QUARTER-warp (8 lanes) per edge; 4 edges per warp-LDG.
// Lane: q = lane>>3 (edge slot), g = lane&7 (col group: 8 fp8 cols = uint2).
// MODE 0: x=seed_q  (w2), den & bctx, update with p=seed  -> propA (+fp8)
// MODE 1: x=prop_q  (w2), update with p=prop[bufin]       -> prop[bufin^1]
// MODE 3: x=prop_q  (w),  prop_ctx + fused accept/blend   -> out
template <int MODE>
__global__ void __launch_bounds__(256) k_fused(int bufin, float* __restrict__ outp) {
    int warp = (blockIdx.x * blockDim.x + threadIdx.x) >> 5;
    if (warp >= NN) return;
    int lane = threadIdx.x & 31;
    int q    = lane >> 3;
    int g    = lane & 7;
    const uint2* __restrict__ xq2 =
        (MODE == 0) ? reinterpret_cast<const uint2*>(g_seed_q)
                    : reinterpret_cast<const uint2*>(bufin ? g_propBq : g_propAq);
    int beg = g_off[warp], end = g_off[warp + 1];
    float a0 = 0.f, a1 = 0.f, a2 = 0.f, a3 = 0.f;
    float a4 = 0.f, a5 = 0.f, a6 = 0.f, a7 = 0.f;
    float b0 = 0.f, b1 = 0.f, b2 = 0.f, b3 = 0.f;
    float b4 = 0.f, b5 = 0.f, b6 = 0.f, b7 = 0.f;
    float dacc = 0.f;
    float dmask = (g == 0) ? 1.f : 0.f;   // one lane per quarter counts each edge

    int e = beg;
    // main loop: 8 edges per iteration (2 quads, MLP=2 on the rec->row chain)
    for (; e + 8 <= end; e += 8) {
        int2 rec0 = __ldg(&g_edge[e + q]);
        int2 rec1 = __ldg(&g_edge[e + 4 + q]);
        uint2 v0 = __ldg(&xq2[(size_t)rec0.x * 8 + g]);
        uint2 v1 = __ldg(&xq2[(size_t)rec1.x * 8 + g]);
        __half2 wp0 = *reinterpret_cast<__half2*>(&rec0.y);
        __half2 wp1 = *reinterpret_cast<__half2*>(&rec1.y);
        float w0  = __low2float(wp0),  w20 = __high2float(wp0);
        float w1  = __low2float(wp1),  w21 = __high2float(wp1);
        float4 fA0 = fp8x4_to_float4(v0.x);
        float4 fB0 = fp8x4_to_float4(v0.y);
        float4 fA1 = fp8x4_to_float4(v1.x);
        float4 fB1 = fp8x4_to_float4(v1.y);
        float wa0 = (MODE == 3) ? w0 : w20;
        float wa1 = (MODE == 3) ? w1 : w21;
        a0 = fmaf(wa0, fA0.x, a0); a1 = fmaf(wa0, fA0.y, a1);
        a2 = fmaf(wa0, fA0.z, a2); a3 = fmaf(wa0, fA0.w, a3);
        a4 = fmaf(wa0, fB0.x, a4); a5 = fmaf(wa0, fB0.y, a5);
        a6 = fmaf(wa0, fB0.z, a6); a7 = fmaf(wa0, fB0.w, a7);
        a0 = fmaf(wa1, fA1.x, a0); a1 = fmaf(wa1, fA1.y, a1);
        a2 = fmaf(wa1, fA1.z, a2); a3 = fmaf(wa1, fA1.w, a3);
        a4 = fmaf(wa1, fB1.x, a4); a5 = fmaf(wa1, fB1.y, a5);
        a6 = fmaf(wa1, fB1.z, a6); a7 = fmaf(wa1, fB1.w, a7);
        if (MODE == 0) {
            dacc += dmask * (w20 + w21);
            b0 = fmaf(w0, fA0.x, b0); b1 = fmaf(w0, fA0.y, b1);
            b2 = fmaf(w0, fA0.z, b2); b3 = fmaf(w0, fA0.w, b3);
            b4 = fmaf(w0, fB0.x, b4); b5 = fmaf(w0, fB0.y, b5);
            b6 = fmaf(w0, fB0.z, b6); b7 = fmaf(w0, fB0.w, b7);
            b0 = fmaf(w1, fA1.x, b0); b1 = fmaf(w1, fA1.y, b1);
            b2 = fmaf(w1, fA1.z, b2); b3 = fmaf(w1, fA1.w, b3);
            b4 = fmaf(w1, fB1.x, b4); b5 = fmaf(w1, fB1.y, b5);
            b6 = fmaf(w1, fB1.z, b6); b7 = fmaf(w1, fB1.w, b7);
        }
    }
    // tail: up to 7 edges in masked quads
    for (; e < end; e += 4) {
        int idx = e + q;
        bool valid = idx < end;
        int2 rec = __ldg(&g_edge[valid ? idx : beg]);
        __half2 wp = *reinterpret_cast<__half2*>(&rec.y);
        float w  = valid ? __low2float(wp)  : 0.f;
        float w2 = valid ? __high2float(wp) : 0.f;
        uint2 v = __ldg(&xq2[(size_t)rec.x * 8 + g]);
        float4 fA = fp8x4_to_float4(v.x);
        float4 fB = fp8x4_to_float4(v.y);
        float wa = (MODE == 3) ? w : w2;
        a0 = fmaf(wa, fA.x, a0); a1 = fmaf(wa, fA.y, a1);
        a2 = fmaf(wa, fA.z, a2); a3 = fmaf(wa, fA.w, a3);
        a4 = fmaf(wa, fB.x, a4); a5 = fmaf(wa, fB.y, a5);
        a6 = fmaf(wa, fB.z, a6); a7 = fmaf(wa, fB.w, a7);
        if (MODE == 0) {
            dacc += dmask * w2;
            b0 = fmaf(w, fA.x, b0); b1 = fmaf(w, fA.y, b1);
            b2 = fmaf(w, fA.z, b2); b3 = fmaf(w, fA.w, b3);
            b4 = fmaf(w, fB.x, b4); b5 = fmaf(w, fB.y, b5);
            b6 = fmaf(w, fB.z, b6); b7 = fmaf(w, fB.w, b7);
        }
    }

    // reduce across the 4 quarters (lanes {g, g+8, g+16, g+24})
    #define QRED(x) do { \
        x += __shfl_xor_sync(0xffffffffu, x, 8);  \
        x += __shfl_xor_sync(0xffffffffu, x, 16); \
    } while (0)
    QRED(a0); QRED(a1); QRED(a2); QRED(a3);
    QRED(a4); QRED(a5); QRED(a6); QRED(a7);
    if (MODE == 0) {
        QRED(b0); QRED(b1); QRED(b2); QRED(b3);
        QRED(b4); QRED(b5); QRED(b6); QRED(b7);
    }
    #undef QRED

    size_t row = (size_t)warp * NC;
    const float4* seedv = reinterpret_cast<const float4*>(g_seed + row);
    float4 sa = seedv[2 * g], sb = seedv[2 * g + 1];
    float m = (lane < 8) ? 1.f : 0.f;   // kill 4x duplication in warp sums

    if (MODE == 0 || MODE == 1) {
        float den;
        if (MODE == 0) {
            den = wsum(dacc);
            if (lane == 0) g_den[warp] = den;
        } else {
            den = g_den[warp];
        }
        const float* __restrict__ pin =
            (MODE == 0) ? g_seed : (bufin ? g_propB : g_propA);
        const float4* pinv = reinterpret_cast<const float4*>(pin + row);
        float4 pa = (MODE == 0) ? sa : pinv[2 * g];
        float4 pb = (MODE == 0) ? sb : pinv[2 * g + 1];
        float4 ga = reinterpret_cast<const float4*>(g_gp)[2 * g];
        float4 gb = reinterpret_cast<const float4*>(g_gp)[2 * g + 1];
        float inv = 1.f / fmaxf(den, 1e-8f);
        float f0 = 0.95f * a0 * inv + 0.05f * ga.x;
        float f1 = 0.95f * a1 * inv + 0.05f * ga.y;
        float f2 = 0.95f * a2 * inv + 0.05f * ga.z;
        float f3 = 0.95f * a3 * inv + 0.05f * ga.w;
        float f4 = 0.95f * a4 * inv + 0.05f * gb.x;
        float f5 = 0.95f * a5 * inv + 0.05f * gb.y;
        float f6 = 0.95f * a6 * inv + 0.05f * gb.z;
        float f7 = 0.95f * a7 * inv + 0.05f * gb.w;
        float pf  = wsum(m * (pa.x*f0 + pa.y*f1 + pa.z*f2 + pa.w*f3 +
                              pb.x*f4 + pb.y*f5 + pb.z*f6 + pb.w*f7));
        float pp  = wsum(m * (pa.x*pa.x + pa.y*pa.y + pa.z*pa.z + pa.w*pa.w +
                              pb.x*pb.x + pb.y*pb.y + pb.z*pb.z + pb.w*pb.w));
        float ff  = wsum(m * (f0*f0 + f1*f1 + f2*f2 + f3*f3 +
                              f4*f4 + f5*f5 + f6*f6 + f7*f7));
        float sfd = wsum(m * (sa.x*f0 + sa.y*f1 + sa.z*f2 + sa.w*f3 +
                              sb.x*f4 + sb.y*f5 + sb.z*f6 + sb.w*f7));
        float ss  = wsum(m * (sa.x*sa.x + sa.y*sa.y + sa.z*sa.z + sa.w*sa.w +
                              sb.x*sb.x + sb.y*sb.y + sb.z*sb.z + sb.w*sb.w));
        float np = fmaxf(sqrtf(pp), 1e-8f);
        float nf = fmaxf(sqrtf(ff), 1e-8f);
        float ns = fmaxf(sqrtf(ss), 1e-8f);
        float agree  = clamp01((pf  / (np * nf) + 1.f) * 0.5f);
        float sagree = clamp01((sfd / (ns * nf) + 1.f) * 0.5f);
        float sel    = clamp01(g_selb[warp] + 0.2f * sagree);
        float anchor = g_anchor[warp];
        float ug = g_rgate[warp] * sel * agree * (1.f - anchor);
        float rc = 0.15f * g_scal[3] * ug;
        float ia = 1.f - anchor;
        float o0 = fmaxf(anchor*sa.x + ia*pa.x + rc*(f0 - pa.x), 0.f);
        float o1 = fmaxf(anchor*sa.y + ia*pa.y + rc*(f1 - pa.y), 0.f);
        float o2 = fmaxf(anchor*sa.z + ia*pa.z + rc*(f2 - pa.z), 0.f);
        float o3 = fmaxf(anchor*sa.w + ia*pa.w + rc*(f3 - pa.w), 0.f);
        float o4 = fmaxf(anchor*sb.x + ia*pb.x + rc*(f4 - pb.x), 0.f);
        float o5 = fmaxf(anchor*sb.y + ia*pb.y + rc*(f5 - pb.y), 0.f);
        float o6 = fmaxf(anchor*sb.z + ia*pb.z + rc*(f6 - pb.z), 0.f);
        float o7 = fmaxf(anchor*sb.w + ia*pb.w + rc*(f7 - pb.w), 0.f);
        int outb = (MODE == 0) ? 0 : (bufin ^ 1);
        float*   pout_f = outb ? g_propB  : g_propA;
        uint8_t* pout_q = outb ? g_propBq : g_propAq;
        if (lane < 8) {
            float4* po = reinterpret_cast<float4*>(pout_f + row);
            po[2 * g]     = make_float4(o0, o1, o2, o3);
            po[2 * g + 1] = make_float4(o4, o5, o6, o7);
            uint2 qv;
            qv.x = float4_to_fp8x4(o0, o1, o2, o3);
            qv.y = float4_to_fp8x4(o4, o5, o6, o7);
            reinterpret_cast<uint2*>(pout_q + row)[g] = qv;
            if (MODE == 0) {
                float4* bo = reinterpret_cast<float4*>(g_bctx + row);
                bo[2 * g]     = make_float4(b0, b1, b2, b3);
                bo[2 * g + 1] = make_float4(b4, b5, b6, b7);
            }
        }
    } else {
        // MODE 3: accept & blend. a0..a7 = prop_ctx cols.
        const float* __restrict__ pin = bufin ? g_propB : g_propA;
        const float4* pinv = reinterpret_cast<const float4*>(pin + row);
        float4 pa = pinv[2 * g], pb = pinv[2 * g + 1];
        const float4* bcv = reinterpret_cast<const float4*>(g_bctx + row);
        float4 ba = bcv[2 * g], bb4 = bcv[2 * g + 1];
        float sbc = wsum(m * (sa.x*ba.x + sa.y*ba.y + sa.z*ba.z + sa.w*ba.w +
                              sb.x*bb4.x + sb.y*bb4.y + sb.z*bb4.z + sb.w*bb4.w));
        float ss  = wsum(m * (sa.x*sa.x + sa.y*sa.y + sa.z*sa.z + sa.w*sa.w +
                              sb.x*sb.x + sb.y*sb.y + sb.z*sb.z + sb.w*sb.w));
        float bb  = wsum(m * (ba.x*ba.x + ba.y*ba.y + ba.z*ba.z + ba.w*ba.w +
                              bb4.x*bb4.x + bb4.y*bb4.y + bb4.z*bb4.z + bb4.w*bb4.w));
        float ppc = wsum(m * (pa.x*a0 + pa.y*a1 + pa.z*a2 + pa.w*a3 +
                              pb.x*a4 + pb.y*a5 + pb.z*a6 + pb.w*a7));
        float pp  = wsum(m * (pa.x*pa.x + pa.y*pa.y + pa.z*pa.z + pa.w*pa.w +
                              pb.x*pb.x + pb.y*pb.y + pb.z*pb.z + pb.w*pb.w));
        float cc  = wsum(m * (a0*a0 + a1*a1 + a2*a2 + a3*a3 +
                              a4*a4 + a5*a5 + a6*a6 + a7*a7));
        float ms  = wsum(m * (sa.x + sa.y + sa.z + sa.w + sb.x + sb.y + sb.z + sb.w));
        float mp  = wsum(m * (pa.x + pa.y + pa.z + pa.w + pb.x + pb.y + pb.z + pb.w));
        // per-lane top2 of 8, masked to -inf on duplicate lanes, warp top2
        float s1 = -1e30f, s2 = -1e30f, p1 = -1e30f, p2 = -1e30f;
        top2_ins(sa.x, s1, s2); top2_ins(sa.y, s1, s2);
        top2_ins(sa.z, s1, s2); top2_ins(sa.w, s1, s2);
        top2_ins(sb.x, s1, s2); top2_ins(sb.y, s1, s2);
        top2_ins(sb.z, s1, s2); top2_ins(sb.w, s1, s2);
        top2_ins(pa.x, p1, p2); top2_ins(pa.y, p1, p2);
        top2_ins(pa.z, p1, p2); top2_ins(pa.w, p1, p2);
        top2_ins(pb.x, p1, p2); top2_ins(pb.y, p1, p2);
        top2_ins(pb.z, p1, p2); top2_ins(pb.w, p1, p2);
        if (lane >= 8) { s1 = -1e30f; s2 = -1e30f; p1 = -1e30f; p2 = -1e30f; }
        wtop2(s1, s2);
        wtop2(p1, p2);
        float ns_ = fmaxf(sqrtf(ss), 1e-8f);
        float nbc = fmaxf(sqrtf(bb), 1e-8f);
        float np_ = fmaxf(sqrtf(pp), 1e-8f);
        float npc = fmaxf(sqrtf(cc), 1e-8f);
        float lqb = clamp01((sbc / (ns_ * nbc) + 1.f) * 0.5f);
        float lqp = clamp01((ppc / (np_ * npc) + 1.f) * 0.5f);
        float mb  = (s1 - s2) / (ms + 1e-8f);
        float mpg = (p1 - p2) / (mp + 1e-8f);
        // clustering term cancels in qp - qb
        float accept = sigmoidf(12.f * ((0.7f * lqp + 0.2f * mpg) -
                                        (0.7f * lqb + 0.2f * mb)));
        if (lane < 8) {
            float4* po = reinterpret_cast<float4*>(outp + row);
            po[2 * g] = make_float4(accept * pa.x + (1.f - accept) * sa.x,
                                    accept * pa.y + (1.f - accept) * sa.y,
                                    accept * pa.z + (1.f - accept) * sa.z,
                                    accept * pa.w + (1.f - accept) * sa.w);
            po[2 * g + 1] = make_float4(accept * pb.x + (1.f - accept) * sb.x,
                                        accept * pb.y + (1.f - accept) * sb.y,
                                        accept * pb.z + (1.f - accept) * sb.z,
                                        accept * pb.w + (1.f - accept) * sb.w);
        }
    }
}

// ---------------- launch ----------------------------------------------------
extern "C" void kernel_launch(void* const* d_in, const int* in_sizes, int n_in,
                              void* d_out, int out_size) {
    (void)in_sizes; (void)n_in; (void)out_size;
    const float* logits = (const float*)d_in[0];
    const int*   esrc   = (const int*)d_in[1];
    const int*   edst   = (const int*)d_in[2];
    const float* ew     = (const float*)d_in[3];
    const float* sf     = (const float*)d_in[4];
    float* out = (float*)d_out;

    const int NODE_BLOCKS = (NN + 7) / 8;   // warp per node, 8 warps/block

    k_seed<<<NB, 256>>>(logits, sf);
    k_conf<<<NB, 256>>>(sf);
    k_hist<<<(NE + 511) / 512, 512>>>(edst);
    k_scan1<<<NCH, 1024>>>();
    k_scan2<<<1, 128>>>();
    k_scan3<<<(NN + 255) / 256, 256>>>();
    k_scat<<<(NE + 511) / 512, 512>>>(esrc, edst, ew);

    k_fused<0><<<NODE_BLOCKS, 256>>>(0, out);  // seed gather + update1 -> A
    k_fused<1><<<NODE_BLOCKS, 256>>>(0, out);  // A -> update2 -> B
    k_fused<1><<<NODE_BLOCKS, 256>>>(1, out);  // B -> update3 -> A
    k_fused<3><<<NODE_BLOCKS, 256>>>(0, out);  // prop_ctx(A) + accept -> out
}

// round 12
// speedup vs baseline: 1.0001x; 1.0001x over previous
#include <cuda_runtime.h>
#include <cuda_fp16.h>
#include <cuda_fp8.h>
#include <math.h>
#include <stdint.h>

#define NN 100000
#define NC 64
#define NE 3200000
#define NB 400          // blocks for node-elementwise kernels (256 thr)
#define NCH 98          // ceil(NN/1024) scan chunks

// ---------------- scratch (static __device__ — no allocations allowed) ------
__device__ float   g_seed  [(size_t)NN * NC];
__device__ uint8_t g_seed_q[(size_t)NN * NC];     // e4m3
__device__ float   g_propA [(size_t)NN * NC];
__device__ float   g_propB [(size_t)NN * NC];
__device__ uint8_t g_propAq[(size_t)NN * NC];     // e4m3
__device__ uint8_t g_propBq[(size_t)NN * NC];     // e4m3
__device__ float   g_bctx  [(size_t)NN * NC];
__device__ float   g_mass[NN], g_ent[NN];
__device__ float   g_sgate[NN], g_rgate[NN], g_anchor[NN], g_selb[NN], g_den[NN];
__device__ int     g_hist[NN];
__device__ int     g_off[NN + 1];
__device__ int     g_cur[NN];
__device__ int2    g_edge[NE];                    // {src, half2(w, w*sgate[src])}
__device__ int     g_csum[NCH], g_cbase[NCH];
__device__ float   g_pmass[NB], g_pclust[NB];
__device__ float   g_scal[4];                     // 2: conf_sum, 3: graph_scale
__device__ float   g_gp[NC];

// ---------------- helpers ---------------------------------------------------
__device__ __forceinline__ float wsum(float v) {
    #pragma unroll
    for (int o = 16; o; o >>= 1) v += __shfl_xor_sync(0xffffffffu, v, o);
    return v;
}
__device__ __forceinline__ void wtop2(float& m1, float& m2) {
    #pragma unroll
    for (int o = 16; o; o >>= 1) {
        float o1 = __shfl_xor_sync(0xffffffffu, m1, o);
        float o2 = __shfl_xor_sync(0xffffffffu, m2, o);
        float hi = fmaxf(m1, o1);
        float lo = fmaxf(fminf(m1, o1), fmaxf(m2, o2));
        m1 = hi; m2 = lo;
    }
}
__device__ __forceinline__ float clamp01(float x) { return fminf(fmaxf(x, 0.f), 1.f); }
__device__ __forceinline__ float sigmoidf(float x) { return 1.f / (1.f + expf(-x)); }

// 4 × e4m3 (packed u32, ch0 = low byte) -> 4 floats  (cuda_fp8.h intrinsics)
__device__ __forceinline__ float4 fp8x4_to_float4(uint32_t v) {
    __nv_fp8x2_storage_t lo = (__nv_fp8x2_storage_t)(v & 0xffffu);
    __nv_fp8x2_storage_t hi = (__nv_fp8x2_storage_t)(v >> 16);
    __half2_raw h01 = __nv_cvt_fp8x2_to_halfraw2(lo, __NV_E4M3);
    __half2_raw h23 = __nv_cvt_fp8x2_to_halfraw2(hi, __NV_E4M3);
    float2 f01 = __half22float2(*reinterpret_cast<__half2*>(&h01));
    float2 f23 = __half22float2(*reinterpret_cast<__half2*>(&h23));
    return make_float4(f01.x, f01.y, f23.x, f23.y);
}
// 4 floats -> packed 4 × e4m3 (c0 in lowest byte)
__device__ __forceinline__ uint32_t float4_to_fp8x4(float c0, float c1, float c2, float c3) {
    __nv_fp8x2_storage_t lo =
        __nv_cvt_float2_to_fp8x2(make_float2(c0, c1), __NV_SATFINITE, __NV_E4M3);
    __nv_fp8x2_storage_t hi =
        __nv_cvt_float2_to_fp8x2(make_float2(c2, c3), __NV_SATFINITE, __NV_E4M3);
    return (uint32_t)lo | ((uint32_t)hi << 16);
}
__device__ __forceinline__ unsigned short float2_to_fp8x2(float c0, float c1) {
    return (unsigned short)
        __nv_cvt_float2_to_fp8x2(make_float2(c0, c1), __NV_SATFINITE, __NV_E4M3);
}
// running top2 insert
__device__ __forceinline__ void top2_ins(float v, float& m1, float& m2) {
    float nm1 = fmaxf(m1, v);
    m2 = fmaxf(m2, fminf(m1, v));
    m1 = nm1;
}

// ---------------- kernels ---------------------------------------------------
// seed = relu(logits); mass/entropy; partial sums; zero hist/gp/scal
__global__ void __launch_bounds__(256) k_seed(const float* __restrict__ logits,
                                              const float* __restrict__ sf) {
    __shared__ float sm_mass[8], sm_clust[8];
    int t = blockIdx.x * blockDim.x + threadIdx.x;
    if (t < NN) g_hist[t] = 0;
    if (t < NC) g_gp[t] = 0.f;
    if (t < 4)  g_scal[t] = 0.f;
    int warp = t >> 5;
    int lane = threadIdx.x & 31;
    int wib  = threadIdx.x >> 5;
    int nw   = (gridDim.x * blockDim.x) >> 5;
    float lmass = 0.f, lclust = 0.f;
    for (int n = warp; n < NN; n += nw) {
        float2 lg = reinterpret_cast<const float2*>(logits + (size_t)n * NC)[lane];
        float2 s  = make_float2(fmaxf(lg.x, 0.f), fmaxf(lg.y, 0.f));
        reinterpret_cast<float2*>(g_seed + (size_t)n * NC)[lane] = s;
        reinterpret_cast<unsigned short*>(g_seed_q + (size_t)n * NC)[lane] =
            float2_to_fp8x2(s.x, s.y);
        float mass = wsum(s.x + s.y);
        float inv  = 1.f / (mass + 1e-8f);
        float nx = s.x * inv, ny = s.y * inv;
        float e   = -(nx * logf(nx + 1e-8f) + ny * logf(ny + 1e-8f));
        float ent = wsum(e);
        if (lane == 0) {
            g_mass[n] = mass; g_ent[n] = ent;
            lmass += mass; lclust += sf[2 * n + 1];
        }
    }
    if (lane == 0) { sm_mass[wib] = lmass; sm_clust[wib] = lclust; }
    __syncthreads();
    if (threadIdx.x == 0) {
        float m = 0.f, c = 0.f;
        #pragma unroll
        for (int i = 0; i < 8; i++) { m += sm_mass[i]; c += sm_clust[i]; }
        g_pmass[blockIdx.x] = m; g_pclust[blockIdx.x] = c;
    }
}

// confidence, gates, anchor, selective-base; global prior numerator & conf sum
__global__ void __launch_bounds__(256) k_conf(const float* __restrict__ sf) {
    __shared__ float sm[256];
    float acc = 0.f;
    for (int i = threadIdx.x; i < NB; i += 256) acc += g_pmass[i];
    sm[threadIdx.x] = acc;
    __syncthreads();
    for (int o = 128; o; o >>= 1) {
        if (threadIdx.x < o) sm[threadIdx.x] += sm[threadIdx.x + o];
        __syncthreads();
    }
    float scale = fmaxf(sm[0] * (1.f / (float)NN), 1e-8f);
    __syncthreads();

    int warp = (blockIdx.x * blockDim.x + threadIdx.x) >> 5;
    int lane = threadIdx.x & 31;
    int nw   = (gridDim.x * blockDim.x) >> 5;
    const float invlog = 1.f / logf(64.f);
    float2 gpacc = make_float2(0.f, 0.f);
    float lconf = 0.f;
    for (int n = warp; n < NN; n += nw) {
        float mass = g_mass[n], ent = g_ent[n];
        float cert = 1.f - ent * invlog;
        float mag  = tanhf(mass / scale);
        float conf = clamp01(0.5f * cert + 0.5f * mag);
        float2 s = reinterpret_cast<const float2*>(g_seed + (size_t)n * NC)[lane];
        gpacc.x += conf * s.x;  gpacc.y += conf * s.y;
        if (lane == 0) {
            lconf += conf;
            g_sgate[n]  = sigmoidf(8.f * (conf - 0.55f));
            g_rgate[n]  = sigmoidf(8.f * (0.5f - conf));
            g_anchor[n] = fminf(fmaxf(0.6f + 0.2f * conf, 0.f), 0.995f);
            float ld = clamp01(1.f - sf[2 * n + 0]);
            float lc = clamp01(1.f - sf[2 * n + 1]);
            g_selb[n] = (1.f - conf) + 0.25f * ld + 0.2f * lc;
        }
    }
    atomicAdd(&g_gp[2 * lane + 0], gpacc.x);
    atomicAdd(&g_gp[2 * lane + 1], gpacc.y);
    if (lane == 0) atomicAdd(&g_scal[2], lconf);
}

// histogram of dst + finalize global prior & graph_scale
__global__ void k_hist(const int* __restrict__ dst) {
    if (blockIdx.x == 0 && threadIdx.x == 0) {
        float c = 0.f;
        for (int i = 0; i < NB; i++) c += g_pclust[i];
        g_scal[3] = fminf(fmaxf(1.f - c * (1.f / (float)NN), 0.2f), 1.f);
    }
    if (blockIdx.x == 1 && threadIdx.x < NC) {
        g_gp[threadIdx.x] /= fmaxf(g_scal[2], 1e-8f);
    }
    int e = blockIdx.x * blockDim.x + threadIdx.x;
    int stride = gridDim.x * blockDim.x;
    for (; e < NE; e += stride) atomicAdd(&g_hist[dst[e]], 1);
}

// ---- parallel 3-phase exclusive scan of g_hist -> g_off, g_cur -------------
__global__ void __launch_bounds__(1024) k_scan1() {
    __shared__ int wsums[32];
    int tid = threadIdx.x;
    int lane = tid & 31;
    int i = blockIdx.x * 1024 + tid;
    int v = (i < NN) ? g_hist[i] : 0;
    int x = v;
    #pragma unroll
    for (int o = 1; o < 32; o <<= 1) {
        int t = __shfl_up_sync(0xffffffffu, x, o);
        if (lane >= o) x += t;
    }
    if (lane == 31) wsums[tid >> 5] = x;
    __syncthreads();
    if (tid < 32) {
        int s = wsums[tid];
        #pragma unroll
        for (int o = 1; o < 32; o <<= 1) {
            int t = __shfl_up_sync(0xffffffffu, s, o);
            if (lane >= o) s += t;
        }
        wsums[tid] = s;
    }
    __syncthreads();
    int base = (tid >= 32) ? wsums[(tid >> 5) - 1] : 0;
    int inc = x + base;
    if (i < NN) g_off[i] = inc - v;
    if (tid == 1023) g_csum[blockIdx.x] = inc;
}
__global__ void k_scan2() {
    __shared__ int sh[128];
    int tid = threadIdx.x;
    int v = (tid < NCH) ? g_csum[tid] : 0;
    sh[tid] = v;
    __syncthreads();
    for (int o = 1; o < 128; o <<= 1) {
        int t = (tid >= o) ? sh[tid - o] : 0;
        __syncthreads();
        sh[tid] += t;
        __syncthreads();
    }
    if (tid < NCH) g_cbase[tid] = sh[tid] - v;
}
__global__ void k_scan3() {
    int i = blockIdx.x * blockDim.x + threadIdx.x;
    if (i < NN) {
        int off = g_off[i] + g_cbase[i >> 10];
        g_off[i] = off;
        g_cur[i] = off;
    }
    if (i == 0) g_off[NN] = NE;
}

// scatter into dst-sorted 8B edge records {src, half2(w, w*sgate[src])}
__global__ void k_scat(const int* __restrict__ src, const int* __restrict__ dst,
                       const float* __restrict__ w) {
    int e = blockIdx.x * blockDim.x + threadIdx.x;
    int stride = gridDim.x * blockDim.x;
    for (; e < NE; e += stride) {
        int d = dst[e];
        int s = src[e];
        float wv = w[e];
        float sg = g_sgate[s];
        int pos = atomicAdd(&g_cur[d], 1);
        __half2 hp = __halves2half2(__float2half_rn(wv),
                                    __float2half_rn(wv * sg));
        int2 rec;
        rec.x = s;
        rec.y = *reinterpret_cast<int*>(&hp);
        g_edge[pos] = rec;
    }
}

// ---------------- fused gather-SPMM + epilogue -------------------------------
// Warp per dst node. QUARTER-warp (8 lanes) per edge; 4 edges per warp-LDG.
// Lane: q = lane>>3 (edge slot), g = lane&7 (col group: 8 fp8 cols = uint2).
// MODE 0: x=seed_q  (w2), den & bctx, update with p=seed  -> propA (+fp8)
// MODE 1: x=prop_q  (w2), update with p=prop[bufin]       -> prop[bufin^1]
// MODE 3: x=prop_q  (w),  prop_ctx + fused accept/blend   -> out
template <int MODE>
__global__ void __launch_bounds__(256) k_fused(int bufin, float* __restrict__ outp) {
    int warp = (blockIdx.x * blockDim.x + threadIdx.x) >> 5;
    if (warp >= NN) return;
    int lane = threadIdx.x & 31;
    int q    = lane >> 3;
    int g    = lane & 7;
    const uint2* __restrict__ xq2 =
        (MODE == 0) ? reinterpret_cast<const uint2*>(g_seed_q)
                    : reinterpret_cast<const uint2*>(bufin ? g_propBq : g_propAq);
    int beg = g_off[warp], end = g_off[warp + 1];
    float a0 = 0.f, a1 = 0.f, a2 = 0.f, a3 = 0.f;
    float a4 = 0.f, a5 = 0.f, a6 = 0.f, a7 = 0.f;
    float b0 = 0.f, b1 = 0.f, b2 = 0.f, b3 = 0.f;
    float b4 = 0.f, b5 = 0.f, b6 = 0.f, b7 = 0.f;
    float dacc = 0.f;
    float dmask = (g == 0) ? 1.f : 0.f;   // one lane per quarter counts each edge

    int e = beg;
    // main loop: 8 edges per iteration (2 quads, MLP=2 on the rec->row chain)
    for (; e + 8 <= end; e += 8) {
        int2 rec0 = __ldg(&g_edge[e + q]);
        int2 rec1 = __ldg(&g_edge[e + 4 + q]);
        uint2 v0 = __ldg(&xq2[(size_t)rec0.x * 8 + g]);
        uint2 v1 = __ldg(&xq2[(size_t)rec1.x * 8 + g]);
        __half2 wp0 = *reinterpret_cast<__half2*>(&rec0.y);
        __half2 wp1 = *reinterpret_cast<__half2*>(&rec1.y);
        float w0  = __low2float(wp0),  w20 = __high2float(wp0);
        float w1  = __low2float(wp1),  w21 = __high2float(wp1);
        float4 fA0 = fp8x4_to_float4(v0.x);
        float4 fB0 = fp8x4_to_float4(v0.y);
        float4 fA1 = fp8x4_to_float4(v1.x);
        float4 fB1 = fp8x4_to_float4(v1.y);
        float wa0 = (MODE == 3) ? w0 : w20;
        float wa1 = (MODE == 3) ? w1 : w21;
        a0 = fmaf(wa0, fA0.x, a0); a1 = fmaf(wa0, fA0.y, a1);
        a2 = fmaf(wa0, fA0.z, a2); a3 = fmaf(wa0, fA0.w, a3);
        a4 = fmaf(wa0, fB0.x, a4); a5 = fmaf(wa0, fB0.y, a5);
        a6 = fmaf(wa0, fB0.z, a6); a7 = fmaf(wa0, fB0.w, a7);
        a0 = fmaf(wa1, fA1.x, a0); a1 = fmaf(wa1, fA1.y, a1);
        a2 = fmaf(wa1, fA1.z, a2); a3 = fmaf(wa1, fA1.w, a3);
        a4 = fmaf(wa1, fB1.x, a4); a5 = fmaf(wa1, fB1.y, a5);
        a6 = fmaf(wa1, fB1.z, a6); a7 = fmaf(wa1, fB1.w, a7);
        if (MODE == 0) {
            dacc += dmask * (w20 + w21);
            b0 = fmaf(w0, fA0.x, b0); b1 = fmaf(w0, fA0.y, b1);
            b2 = fmaf(w0, fA0.z, b2); b3 = fmaf(w0, fA0.w, b3);
            b4 = fmaf(w0, fB0.x, b4); b5 = fmaf(w0, fB0.y, b5);
            b6 = fmaf(w0, fB0.z, b6); b7 = fmaf(w0, fB0.w, b7);
            b0 = fmaf(w1, fA1.x, b0); b1 = fmaf(w1, fA1.y, b1);
            b2 = fmaf(w1, fA1.z, b2); b3 = fmaf(w1, fA1.w, b3);
            b4 = fmaf(w1, fB1.x, b4); b5 = fmaf(w1, fB1.y, b5);
            b6 = fmaf(w1, fB1.z, b6); b7 = fmaf(w1, fB1.w, b7);
        }
    }
    // tail: up to 7 edges in masked quads
    for (; e < end; e += 4) {
        int idx = e + q;
        bool valid = idx < end;
        int2 rec = __ldg(&g_edge[valid ? idx : beg]);
        __half2 wp = *reinterpret_cast<__half2*>(&rec.y);
        float w  = valid ? __low2float(wp)  : 0.f;
        float w2 = valid ? __high2float(wp) : 0.f;
        uint2 v = __ldg(&xq2[(size_t)rec.x * 8 + g]);
        float4 fA = fp8x4_to_float4(v.x);
        float4 fB = fp8x4_to_float4(v.y);
        float wa = (MODE == 3) ? w : w2;
        a0 = fmaf(wa, fA.x, a0); a1 = fmaf(wa, fA.y, a1);
        a2 = fmaf(wa, fA.z, a2); a3 = fmaf(wa, fA.w, a3);
        a4 = fmaf(wa, fB.x, a4); a5 = fmaf(wa, fB.y, a5);
        a6 = fmaf(wa, fB.z, a6); a7 = fmaf(wa, fB.w, a7);
        if (MODE == 0) {
            dacc += dmask * w2;
            b0 = fmaf(w, fA.x, b0); b1 = fmaf(w, fA.y, b1);
            b2 = fmaf(w, fA.z, b2); b3 = fmaf(w, fA.w, b3);
            b4 = fmaf(w, fB.x, b4); b5 = fmaf(w, fB.y, b5);
            b6 = fmaf(w, fB.z, b6); b7 = fmaf(w, fB.w, b7);
        }
    }

    // reduce across the 4 quarters (lanes {g, g+8, g+16, g+24})
    #define QRED(x) do { \
        x += __shfl_xor_sync(0xffffffffu, x, 8);  \
        x += __shfl_xor_sync(0xffffffffu, x, 16); \
    } while (0)
    QRED(a0); QRED(a1); QRED(a2); QRED(a3);
    QRED(a4); QRED(a5); QRED(a6); QRED(a7);
    if (MODE == 0) {
        QRED(b0); QRED(b1); QRED(b2); QRED(b3);
        QRED(b4); QRED(b5); QRED(b6); QRED(b7);
    }
    #undef QRED

    size_t row = (size_t)warp * NC;
    const float4* seedv = reinterpret_cast<const float4*>(g_seed + row);
    float4 sa = seedv[2 * g], sb = seedv[2 * g + 1];
    float m = (lane < 8) ? 1.f : 0.f;   // kill 4x duplication in warp sums

    if (MODE == 0 || MODE == 1) {
        float den;
        if (MODE == 0) {
            den = wsum(dacc);
            if (lane == 0) g_den[warp] = den;
        } else {
            den = g_den[warp];
        }
        const float* __restrict__ pin =
            (MODE == 0) ? g_seed : (bufin ? g_propB : g_propA);
        const float4* pinv = reinterpret_cast<const float4*>(pin + row);
        float4 pa = (MODE == 0) ? sa : pinv[2 * g];
        float4 pb = (MODE == 0) ? sb : pinv[2 * g + 1];
        float4 ga = reinterpret_cast<const float4*>(g_gp)[2 * g];
        float4 gb = reinterpret_cast<const float4*>(g_gp)[2 * g + 1];
        float inv = 1.f / fmaxf(den, 1e-8f);
        float f0 = 0.95f * a0 * inv + 0.05f * ga.x;
        float f1 = 0.95f * a1 * inv + 0.05f * ga.y;
        float f2 = 0.95f * a2 * inv + 0.05f * ga.z;
        float f3 = 0.95f * a3 * inv + 0.05f * ga.w;
        float f4 = 0.95f * a4 * inv + 0.05f * gb.x;
        float f5 = 0.95f * a5 * inv + 0.05f * gb.y;
        float f6 = 0.95f * a6 * inv + 0.05f * gb.z;
        float f7 = 0.95f * a7 * inv + 0.05f * gb.w;
        float pf  = wsum(m * (pa.x*f0 + pa.y*f1 + pa.z*f2 + pa.w*f3 +
                              pb.x*f4 + pb.y*f5 + pb.z*f6 + pb.w*f7));
        float pp  = wsum(m * (pa.x*pa.x + pa.y*pa.y + pa.z*pa.z + pa.w*pa.w +
                              pb.x*pb.x + pb.y*pb.y + pb.z*pb.z + pb.w*pb.w));
        float ff  = wsum(m * (f0*f0 + f1*f1 + f2*f2 + f3*f3 +
                              f4*f4 + f5*f5 + f6*f6 + f7*f7));
        float sfd = wsum(m * (sa.x*f0 + sa.y*f1 + sa.z*f2 + sa.w*f3 +
                              sb.x*f4 + sb.y*f5 + sb.z*f6 + sb.w*f7));
        float ss  = wsum(m * (sa.x*sa.x + sa.y*sa.y + sa.z*sa.z + sa.w*sa.w +
                              sb.x*sb.x + sb.y*sb.y + sb.z*sb.z + sb.w*sb.w));
        float np = fmaxf(sqrtf(pp), 1e-8f);
        float nf = fmaxf(sqrtf(ff), 1e-8f);
        float ns = fmaxf(sqrtf(ss), 1e-8f);
        float agree  = clamp01((pf  / (np * nf) + 1.f) * 0.5f);
        float sagree = clamp01((sfd / (ns * nf) + 1.f) * 0.5f);
        float sel    = clamp01(g_selb[warp] + 0.2f * sagree);
        float anchor = g_anchor[warp];
        float ug = g_rgate[warp] * sel * agree * (1.f - anchor);
        float rc = 0.15f * g_scal[3] * ug;
        float ia = 1.f - anchor;
        float o0 = fmaxf(anchor*sa.x + ia*pa.x + rc*(f0 - pa.x), 0.f);
        float o1 = fmaxf(anchor*sa.y + ia*pa.y + rc*(f1 - pa.y), 0.f);
        float o2 = fmaxf(anchor*sa.z + ia*pa.z + rc*(f2 - pa.z), 0.f);
        float o3 = fmaxf(anchor*sa.w + ia*pa.w + rc*(f3 - pa.w), 0.f);
        float o4 = fmaxf(anchor*sb.x + ia*pb.x + rc*(f4 - pb.x), 0.f);
        float o5 = fmaxf(anchor*sb.y + ia*pb.y + rc*(f5 - pb.y), 0.f);
        float o6 = fmaxf(anchor*sb.z + ia*pb.z + rc*(f6 - pb.z), 0.f);
        float o7 = fmaxf(anchor*sb.w + ia*pb.w + rc*(f7 - pb.w), 0.f);
        int outb = (MODE == 0) ? 0 : (bufin ^ 1);
        float*   pout_f = outb ? g_propB  : g_propA;
        uint8_t* pout_q = outb ? g_propBq : g_propAq;
        if (lane < 8) {
            float4* po = reinterpret_cast<float4*>(pout_f + row);
            po[2 * g]     = make_float4(o0, o1, o2, o3);
            po[2 * g + 1] = make_float4(o4, o5, o6, o7);
            uint2 qv;
            qv.x = float4_to_fp8x4(o0, o1, o2, o3);
            qv.y = float4_to_fp8x4(o4, o5, o6, o7);
            reinterpret_cast<uint2*>(pout_q + row)[g] = qv;
            if (MODE == 0) {
                float4* bo = reinterpret_cast<float4*>(g_bctx + row);
                bo[2 * g]     = make_float4(b0, b1, b2, b3);
                bo[2 * g + 1] = make_float4(b4, b5, b6, b7);
            }
        }
    } else {
        // MODE 3: accept & blend. a0..a7 = prop_ctx cols.
        const float* __restrict__ pin = bufin ? g_propB : g_propA;
        const float4* pinv = reinterpret_cast<const float4*>(pin + row);
        float4 pa = pinv[2 * g], pb = pinv[2 * g + 1];
        const float4* bcv = reinterpret_cast<const float4*>(g_bctx + row);
        float4 ba = bcv[2 * g], bb4 = bcv[2 * g + 1];
        float sbc = wsum(m * (sa.x*ba.x + sa.y*ba.y + sa.z*ba.z + sa.w*ba.w +
                              sb.x*bb4.x + sb.y*bb4.y + sb.z*bb4.z + sb.w*bb4.w));
        float ss  = wsum(m * (sa.x*sa.x + sa.y*sa.y + sa.z*sa.z + sa.w*sa.w +
                              sb.x*sb.x + sb.y*sb.y + sb.z*sb.z + sb.w*sb.w));
        float bb  = wsum(m * (ba.x*ba.x + ba.y*ba.y + ba.z*ba.z + ba.w*ba.w +
                              bb4.x*bb4.x + bb4.y*bb4.y + bb4.z*bb4.z + bb4.w*bb4.w));
        float ppc = wsum(m * (pa.x*a0 + pa.y*a1 + pa.z*a2 + pa.w*a3 +
                              pb.x*a4 + pb.y*a5 + pb.z*a6 + pb.w*a7));
        float pp  = wsum(m * (pa.x*pa.x + pa.y*pa.y + pa.z*pa.z + pa.w*pa.w +
                              pb.x*pb.x + pb.y*pb.y + pb.z*pb.z + pb.w*pb.w));
        float cc  = wsum(m * (a0*a0 + a1*a1 + a2*a2 + a3*a3 +
                              a4*a4 + a5*a5 + a6*a6 + a7*a7));
        float ms  = wsum(m * (sa.x + sa.y + sa.z + sa.w + sb.x + sb.y + sb.z + sb.w));
        float mp  = wsum(m * (pa.x + pa.y + pa.z + pa.w + pb.x + pb.y + pb.z + pb.w));
        // per-lane top2 of 8, masked to -inf on duplicate lanes, warp top2
        float s1 = -1e30f, s2 = -1e30f, p1 = -1e30f, p2 = -1e30f;
        top2_ins(sa.x, s1, s2); top2_ins(sa.y, s1, s2);
        top2_ins(sa.z, s1, s2); top2_ins(sa.w, s1, s2);
        top2_ins(sb.x, s1, s2); top2_ins(sb.y, s1, s2);
        top2_ins(sb.z, s1, s2); top2_ins(sb.w, s1, s2);
        top2_ins(pa.x, p1, p2); top2_ins(pa.y, p1, p2);
        top2_ins(pa.z, p1, p2); top2_ins(pa.w, p1, p2);
        top2_ins(pb.x, p1, p2); top2_ins(pb.y, p1, p2);
        top2_ins(pb.z, p1, p2); top2_ins(pb.w, p1, p2);
        if (lane >= 8) { s1 = -1e30f; s2 = -1e30f; p1 = -1e30f; p2 = -1e30f; }
        wtop2(s1, s2);
        wtop2(p1, p2);
        float ns_ = fmaxf(sqrtf(ss), 1e-8f);
        float nbc = fmaxf(sqrtf(bb), 1e-8f);
        float np_ = fmaxf(sqrtf(pp), 1e-8f);
        float npc = fmaxf(sqrtf(cc), 1e-8f);
        float lqb = clamp01((sbc / (ns_ * nbc) + 1.f) * 0.5f);
        float lqp = clamp01((ppc / (np_ * npc) + 1.f) * 0.5f);
        float mb  = (s1 - s2) / (ms + 1e-8f);
        float mpg = (p1 - p2) / (mp + 1e-8f);
        // clustering term cancels in qp - qb
        float accept = sigmoidf(12.f * ((0.7f * lqp + 0.2f * mpg) -
                                        (0.7f * lqb + 0.2f * mb)));
        if (lane < 8) {
            float4* po = reinterpret_cast<float4*>(outp + row);
            po[2 * g] = make_float4(accept * pa.x + (1.f - accept) * sa.x,
                                    accept * pa.y + (1.f - accept) * sa.y,
                                    accept * pa.z + (1.f - accept) * sa.z,
                                    accept * pa.w + (1.f - accept) * sa.w);
            po[2 * g + 1] = make_float4(accept * pb.x + (1.f - accept) * sb.x,
                                        accept * pb.y + (1.f - accept) * sb.y,
                                        accept * pb.z + (1.f - accept) * sb.z,
                                        accept * pb.w + (1.f - accept) * sb.w);
        }
    }
}

// ---------------- launch ----------------------------------------------------
extern "C" void kernel_launch(void* const* d_in, const int* in_sizes, int n_in,
                              void* d_out, int out_size) {
    (void)in_sizes; (void)n_in; (void)out_size;
    const float* logits = (const float*)d_in[0];
    const int*   esrc   = (const int*)d_in[1];
    const int*   edst   = (const int*)d_in[2];
    const float* ew     = (const float*)d_in[3];
    const float* sf     = (const float*)d_in[4];
    float* out = (float*)d_out;

    const int NODE_BLOCKS = (NN + 7) / 8;   // warp per node, 8 warps/block

    k_seed<<<NB, 256>>>(logits, sf);
    k_conf<<<NB, 256>>>(sf);
    k_hist<<<(NE + 511) / 512, 512>>>(edst);
    k_scan1<<<NCH, 1024>>>();
    k_scan2<<<1, 128>>>();
    k_scan3<<<(NN + 255) / 256, 256>>>();
    k_scat<<<(NE + 511) / 512, 512>>>(esrc, edst, ew);

    k_fused<0><<<NODE_BLOCKS, 256>>>(0, out);  // seed gather + update1 -> A
    k_fused<1><<<NODE_BLOCKS, 256>>>(0, out);  // A -> update2 -> B
    k_fused<1><<<NODE_BLOCKS, 256>>>(1, out);  // B -> update3 -> A
    k_fused<3><<<NODE_BLOCKS, 256>>>(0, out);  // prop_ctx(A) + accept -> out
}

// round 13
// speedup vs baseline: 1.1584x; 1.1583x over previous
#include <cuda_runtime.h>
#include <cuda_fp16.h>
#include <cuda_fp8.h>
#include <math.h>
#include <stdint.h>

#define NN 100000
#define NC 64
#define NE 3200000
#define NB 400          // blocks for node-elementwise kernels (256 thr)
#define NCH 98          // ceil(NN/1024) scan chunks

// ---------------- scratch (static __device__ — no allocations allowed) ------
__device__ float   g_seed  [(size_t)NN * NC];
__device__ uint8_t g_seed_q[(size_t)NN * NC];     // e4m3
__device__ float   g_propA [(size_t)NN * NC];
__device__ float   g_propB [(size_t)NN * NC];
__device__ uint8_t g_propAq[(size_t)NN * NC];     // e4m3
__device__ uint8_t g_propBq[(size_t)NN * NC];     // e4m3
__device__ float   g_bctx  [(size_t)NN * NC];
__device__ float   g_mass[NN], g_ent[NN];
__device__ float   g_sgate[NN], g_rgate[NN], g_anchor[NN], g_selb[NN], g_den[NN];
__device__ int     g_hist[NN];
__device__ int     g_off[NN + 1];
__device__ int     g_cur[NN];
__device__ int2    g_edge[NE];                    // {src, half2(w, w*sgate[src])}
__device__ int     g_csum[NCH], g_cbase[NCH];
__device__ float   g_pmass[NB], g_pclust[NB];
__device__ float   g_scal[4];                     // 2: conf_sum, 3: graph_scale
__device__ float   g_gp[NC];

// ---------------- helpers ---------------------------------------------------
__device__ __forceinline__ float wsum(float v) {
    #pragma unroll
    for (int o = 16; o; o >>= 1) v += __shfl_xor_sync(0xffffffffu, v, o);
    return v;
}
__device__ __forceinline__ void wtop2(float& m1, float& m2) {
    #pragma unroll
    for (int o = 16; o; o >>= 1) {
        float o1 = __shfl_xor_sync(0xffffffffu, m1, o);
        float o2 = __shfl_xor_sync(0xffffffffu, m2, o);
        float hi = fmaxf(m1, o1);
        float lo = fmaxf(fminf(m1, o1), fmaxf(m2, o2));
        m1 = hi; m2 = lo;
    }
}
__device__ __forceinline__ float clamp01(float x) { return fminf(fmaxf(x, 0.f), 1.f); }
__device__ __forceinline__ float sigmoidf(float x) { return 1.f / (1.f + expf(-x)); }

// 4 × e4m3 (packed u32, ch0 = low byte) -> 4 floats  (cuda_fp8.h intrinsics)
__device__ __forceinline__ float4 fp8x4_to_float4(uint32_t v) {
    __nv_fp8x2_storage_t lo = (__nv_fp8x2_storage_t)(v & 0xffffu);
    __nv_fp8x2_storage_t hi = (__nv_fp8x2_storage_t)(v >> 16);
    __half2_raw h01 = __nv_cvt_fp8x2_to_halfraw2(lo, __NV_E4M3);
    __half2_raw h23 = __nv_cvt_fp8x2_to_halfraw2(hi, __NV_E4M3);
    float2 f01 = __half22float2(*reinterpret_cast<__half2*>(&h01));
    float2 f23 = __half22float2(*reinterpret_cast<__half2*>(&h23));
    return make_float4(f01.x, f01.y, f23.x, f23.y);
}
// 4 floats -> packed 4 × e4m3 (c0 in lowest byte)
__device__ __forceinline__ uint32_t float4_to_fp8x4(float c0, float c1, float c2, float c3) {
    __nv_fp8x2_storage_t lo =
        __nv_cvt_float2_to_fp8x2(make_float2(c0, c1), __NV_SATFINITE, __NV_E4M3);
    __nv_fp8x2_storage_t hi =
        __nv_cvt_float2_to_fp8x2(make_float2(c2, c3), __NV_SATFINITE, __NV_E4M3);
    return (uint32_t)lo | ((uint32_t)hi << 16);
}
__device__ __forceinline__ unsigned short float2_to_fp8x2(float c0, float c1) {
    return (unsigned short)
        __nv_cvt_float2_to_fp8x2(make_float2(c0, c1), __NV_SATFINITE, __NV_E4M3);
}

// ---------------- kernels ---------------------------------------------------
// seed = relu(logits); mass/entropy; partial sums; zero hist/gp/scal
__global__ void __launch_bounds__(256) k_seed(const float* __restrict__ logits,
                                              const float* __restrict__ sf) {
    __shared__ float sm_mass[8], sm_clust[8];
    int t = blockIdx.x * blockDim.x + threadIdx.x;
    if (t < NN) g_hist[t] = 0;
    if (t < NC) g_gp[t] = 0.f;
    if (t < 4)  g_scal[t] = 0.f;
    int warp = t >> 5;
    int lane = threadIdx.x & 31;
    int wib  = threadIdx.x >> 5;
    int nw   = (gridDim.x * blockDim.x) >> 5;
    float lmass = 0.f, lclust = 0.f;
    for (int n = warp; n < NN; n += nw) {
        float2 lg = reinterpret_cast<const float2*>(logits + (size_t)n * NC)[lane];
        float2 s  = make_float2(fmaxf(lg.x, 0.f), fmaxf(lg.y, 0.f));
        reinterpret_cast<float2*>(g_seed + (size_t)n * NC)[lane] = s;
        reinterpret_cast<unsigned short*>(g_seed_q + (size_t)n * NC)[lane] =
            float2_to_fp8x2(s.x, s.y);
        float mass = wsum(s.x + s.y);
        float inv  = 1.f / (mass + 1e-8f);
        float nx = s.x * inv, ny = s.y * inv;
        float e   = -(nx * logf(nx + 1e-8f) + ny * logf(ny + 1e-8f));
        float ent = wsum(e);
        if (lane == 0) {
            g_mass[n] = mass; g_ent[n] = ent;
            lmass += mass; lclust += sf[2 * n + 1];
        }
    }
    if (lane == 0) { sm_mass[wib] = lmass; sm_clust[wib] = lclust; }
    __syncthreads();
    if (threadIdx.x == 0) {
        float m = 0.f, c = 0.f;
        #pragma unroll
        for (int i = 0; i < 8; i++) { m += sm_mass[i]; c += sm_clust[i]; }
        g_pmass[blockIdx.x] = m; g_pclust[blockIdx.x] = c;
    }
}

// confidence, gates, anchor, selective-base; global prior numerator & conf sum
__global__ void __launch_bounds__(256) k_conf(const float* __restrict__ sf) {
    __shared__ float sm[256];
    float acc = 0.f;
    for (int i = threadIdx.x; i < NB; i += 256) acc += g_pmass[i];
    sm[threadIdx.x] = acc;
    __syncthreads();
    for (int o = 128; o; o >>= 1) {
        if (threadIdx.x < o) sm[threadIdx.x] += sm[threadIdx.x + o];
        __syncthreads();
    }
    float scale = fmaxf(sm[0] * (1.f / (float)NN), 1e-8f);
    __syncthreads();

    int warp = (blockIdx.x * blockDim.x + threadIdx.x) >> 5;
    int lane = threadIdx.x & 31;
    int nw   = (gridDim.x * blockDim.x) >> 5;
    const float invlog = 1.f / logf(64.f);
    float2 gpacc = make_float2(0.f, 0.f);
    float lconf = 0.f;
    for (int n = warp; n < NN; n += nw) {
        float mass = g_mass[n], ent = g_ent[n];
        float cert = 1.f - ent * invlog;
        float mag  = tanhf(mass / scale);
        float conf = clamp01(0.5f * cert + 0.5f * mag);
        float2 s = reinterpret_cast<const float2*>(g_seed + (size_t)n * NC)[lane];
        gpacc.x += conf * s.x;  gpacc.y += conf * s.y;
        if (lane == 0) {
            lconf += conf;
            g_sgate[n]  = sigmoidf(8.f * (conf - 0.55f));
            g_rgate[n]  = sigmoidf(8.f * (0.5f - conf));
            g_anchor[n] = fminf(fmaxf(0.6f + 0.2f * conf, 0.f), 0.995f);
            float ld = clamp01(1.f - sf[2 * n + 0]);
            float lc = clamp01(1.f - sf[2 * n + 1]);
            g_selb[n] = (1.f - conf) + 0.25f * ld + 0.2f * lc;
        }
    }
    atomicAdd(&g_gp[2 * lane + 0], gpacc.x);
    atomicAdd(&g_gp[2 * lane + 1], gpacc.y);
    if (lane == 0) atomicAdd(&g_scal[2], lconf);
}

// histogram of dst + finalize global prior & graph_scale
__global__ void k_hist(const int* __restrict__ dst) {
    if (blockIdx.x == 0 && threadIdx.x == 0) {
        float c = 0.f;
        for (int i = 0; i < NB; i++) c += g_pclust[i];
        g_scal[3] = fminf(fmaxf(1.f - c * (1.f / (float)NN), 0.2f), 1.f);
    }
    if (blockIdx.x == 1 && threadIdx.x < NC) {
        g_gp[threadIdx.x] /= fmaxf(g_scal[2], 1e-8f);
    }
    int e = blockIdx.x * blockDim.x + threadIdx.x;
    int stride = gridDim.x * blockDim.x;
    for (; e < NE; e += stride) atomicAdd(&g_hist[dst[e]], 1);
}

// ---- parallel 3-phase exclusive scan of g_hist -> g_off, g_cur -------------
__global__ void __launch_bounds__(1024) k_scan1() {
    __shared__ int wsums[32];
    int tid = threadIdx.x;
    int lane = tid & 31;
    int i = blockIdx.x * 1024 + tid;
    int v = (i < NN) ? g_hist[i] : 0;
    int x = v;
    #pragma unroll
    for (int o = 1; o < 32; o <<= 1) {
        int t = __shfl_up_sync(0xffffffffu, x, o);
        if (lane >= o) x += t;
    }
    if (lane == 31) wsums[tid >> 5] = x;
    __syncthreads();
    if (tid < 32) {
        int s = wsums[tid];
        #pragma unroll
        for (int o = 1; o < 32; o <<= 1) {
            int t = __shfl_up_sync(0xffffffffu, s, o);
            if (lane >= o) s += t;
        }
        wsums[tid] = s;
    }
    __syncthreads();
    int base = (tid >= 32) ? wsums[(tid >> 5) - 1] : 0;
    int inc = x + base;
    if (i < NN) g_off[i] = inc - v;
    if (tid == 1023) g_csum[blockIdx.x] = inc;
}
__global__ void k_scan2() {
    __shared__ int sh[128];
    int tid = threadIdx.x;
    int v = (tid < NCH) ? g_csum[tid] : 0;
    sh[tid] = v;
    __syncthreads();
    for (int o = 1; o < 128; o <<= 1) {
        int t = (tid >= o) ? sh[tid - o] : 0;
        __syncthreads();
        sh[tid] += t;
        __syncthreads();
    }
    if (tid < NCH) g_cbase[tid] = sh[tid] - v;
}
__global__ void k_scan3() {
    int i = blockIdx.x * blockDim.x + threadIdx.x;
    if (i < NN) {
        int off = g_off[i] + g_cbase[i >> 10];
        g_off[i] = off;
        g_cur[i] = off;
    }
    if (i == 0) g_off[NN] = NE;
}

// scatter into dst-sorted 8B edge records {src, half2(w, w*sgate[src])}
__global__ void k_scat(const int* __restrict__ src, const int* __restrict__ dst,
                       const float* __restrict__ w) {
    int e = blockIdx.x * blockDim.x + threadIdx.x;
    int stride = gridDim.x * blockDim.x;
    for (; e < NE; e += stride) {
        int d = dst[e];
        int s = src[e];
        float wv = w[e];
        float sg = g_sgate[s];
        int pos = atomicAdd(&g_cur[d], 1);
        __half2 hp = __halves2half2(__float2half_rn(wv),
                                    __float2half_rn(wv * sg));
        int2 rec;
        rec.x = s;
        rec.y = *reinterpret_cast<int*>(&hp);
        g_edge[pos] = rec;
    }
}

// ---------------- fused gather-SPMM + epilogue -------------------------------
// Warp per dst node. Half-warp per edge; edge record read via broadcast LDG.
// Main loop: 8 edges/iter = 4 independent rec-pairs + 4 independent row loads
// in flight (MLP 4 on the latency chain).
// MODE 0: x=seed_q  (w2), den & bctx, update with p=seed  -> propA (+fp8)
// MODE 1: x=prop_q  (w2), update with p=prop[bufin]       -> prop[bufin^1]
// MODE 3: x=prop_q  (w),  prop_ctx + fused accept/blend   -> out
template <int MODE>
__global__ void __launch_bounds__(256) k_fused(int bufin, float* __restrict__ outp) {
    int warp = (blockIdx.x * blockDim.x + threadIdx.x) >> 5;
    if (warp >= NN) return;
    int lane = threadIdx.x & 31;
    int g    = lane & 15;
    int half = lane >> 4;        // 0 or 1: which edge of the pair
    const uint32_t* __restrict__ xq =
        (MODE == 0) ? reinterpret_cast<const uint32_t*>(g_seed_q)
                    : reinterpret_cast<const uint32_t*>(bufin ? g_propBq : g_propAq);
    int beg = g_off[warp], end = g_off[warp + 1];
    float a0 = 0.f, a1 = 0.f, a2 = 0.f, a3 = 0.f;
    float b0 = 0.f, b1 = 0.f, b2 = 0.f, b3 = 0.f;
    float dacc = 0.f;
    float dmask = (g == 0) ? 1.f : 0.f;   // one lane per half counts each edge

    int e = beg;
    // main loop: 8 edges per iteration, 4 independent rec->row chains (MLP 4)
    for (; e + 8 <= end; e += 8) {
        int2 recA = __ldg(&g_edge[e + half]);
        int2 recB = __ldg(&g_edge[e + 2 + half]);
        int2 recC = __ldg(&g_edge[e + 4 + half]);
        int2 recD = __ldg(&g_edge[e + 6 + half]);
        uint32_t vA = __ldg(&xq[(size_t)recA.x * 16 + g]);
        uint32_t vB = __ldg(&xq[(size_t)recB.x * 16 + g]);
        uint32_t vC = __ldg(&xq[(size_t)recC.x * 16 + g]);
        uint32_t vD = __ldg(&xq[(size_t)recD.x * 16 + g]);
        __half2 wpA = *reinterpret_cast<__half2*>(&recA.y);
        __half2 wpB = *reinterpret_cast<__half2*>(&recB.y);
        __half2 wpC = *reinterpret_cast<__half2*>(&recC.y);
        __half2 wpD = *reinterpret_cast<__half2*>(&recD.y);
        float wA  = __low2float(wpA),  w2A = __high2float(wpA);
        float wB  = __low2float(wpB),  w2B = __high2float(wpB);
        float wC  = __low2float(wpC),  w2C = __high2float(wpC);
        float wD  = __low2float(wpD),  w2D = __high2float(wpD);
        float4 fA = fp8x4_to_float4(vA);
        float4 fB = fp8x4_to_float4(vB);
        float4 fC = fp8x4_to_float4(vC);
        float4 fD = fp8x4_to_float4(vD);
        float waA = (MODE == 3) ? wA : w2A;
        float waB = (MODE == 3) ? wB : w2B;
        float waC = (MODE == 3) ? wC : w2C;
        float waD = (MODE == 3) ? wD : w2D;
        a0 = fmaf(waA, fA.x, a0); a1 = fmaf(waA, fA.y, a1);
        a2 = fmaf(waA, fA.z, a2); a3 = fmaf(waA, fA.w, a3);
        a0 = fmaf(waB, fB.x, a0); a1 = fmaf(waB, fB.y, a1);
        a2 = fmaf(waB, fB.z, a2); a3 = fmaf(waB, fB.w, a3);
        a0 = fmaf(waC, fC.x, a0); a1 = fmaf(waC, fC.y, a1);
        a2 = fmaf(waC, fC.z, a2); a3 = fmaf(waC, fC.w, a3);
        a0 = fmaf(waD, fD.x, a0); a1 = fmaf(waD, fD.y, a1);
        a2 = fmaf(waD, fD.z, a2); a3 = fmaf(waD, fD.w, a3);
        if (MODE == 0) {
            dacc += dmask * ((w2A + w2B) + (w2C + w2D));
            b0 = fmaf(wA, fA.x, b0); b1 = fmaf(wA, fA.y, b1);
            b2 = fmaf(wA, fA.z, b2); b3 = fmaf(wA, fA.w, b3);
            b0 = fmaf(wB, fB.x, b0); b1 = fmaf(wB, fB.y, b1);
            b2 = fmaf(wB, fB.z, b2); b3 = fmaf(wB, fB.w, b3);
            b0 = fmaf(wC, fC.x, b0); b1 = fmaf(wC, fC.y, b1);
            b2 = fmaf(wC, fC.z, b2); b3 = fmaf(wC, fC.w, b3);
            b0 = fmaf(wD, fD.x, b0); b1 = fmaf(wD, fD.y, b1);
            b2 = fmaf(wD, fD.z, b2); b3 = fmaf(wD, fD.w, b3);
        }
    }
    // tail: up to 7 edges, processed in masked pairs
    for (; e < end; e += 2) {
        int idx = e + half;
        bool valid = idx < end;
        int2 rec = __ldg(&g_edge[valid ? idx : beg]);
        __half2 wp = *reinterpret_cast<__half2*>(&rec.y);
        float w  = valid ? __low2float(wp)  : 0.f;
        float w2 = valid ? __high2float(wp) : 0.f;
        uint32_t v = __ldg(&xq[(size_t)rec.x * 16 + g]);
        float4 f = fp8x4_to_float4(v);
        float wa = (MODE == 3) ? w : w2;
        a0 = fmaf(wa, f.x, a0); a1 = fmaf(wa, f.y, a1);
        a2 = fmaf(wa, f.z, a2); a3 = fmaf(wa, f.w, a3);
        if (MODE == 0) {
            dacc += dmask * w2;
            b0 = fmaf(w, f.x, b0); b1 = fmaf(w, f.y, b1);
            b2 = fmaf(w, f.z, b2); b3 = fmaf(w, f.w, b3);
        }
    }

    a0 += __shfl_xor_sync(0xffffffffu, a0, 16);
    a1 += __shfl_xor_sync(0xffffffffu, a1, 16);
    a2 += __shfl_xor_sync(0xffffffffu, a2, 16);
    a3 += __shfl_xor_sync(0xffffffffu, a3, 16);
    if (MODE == 0) {
        b0 += __shfl_xor_sync(0xffffffffu, b0, 16);
        b1 += __shfl_xor_sync(0xffffffffu, b1, 16);
        b2 += __shfl_xor_sync(0xffffffffu, b2, 16);
        b3 += __shfl_xor_sync(0xffffffffu, b3, 16);
    }
    size_t row = (size_t)warp * NC;
    float4 s4 = *reinterpret_cast<const float4*>(g_seed + row + 4 * g);
    float m = (lane < 16) ? 1.f : 0.f;   // kill duplicate half in reductions

    if (MODE == 0 || MODE == 1) {
        float den;
        if (MODE == 0) {
            den = wsum(dacc);
            if (lane == 0) g_den[warp] = den;
        } else {
            den = g_den[warp];
        }
        const float* __restrict__ pin =
            (MODE == 0) ? g_seed : (bufin ? g_propB : g_propA);
        float4 p4 = (MODE == 0) ? s4
                  : *reinterpret_cast<const float4*>(pin + row + 4 * g);
        float4 gp4 = reinterpret_cast<const float4*>(g_gp)[g];
        float inv = 1.f / fmaxf(den, 1e-8f);
        float f0 = 0.95f * a0 * inv + 0.05f * gp4.x;
        float f1 = 0.95f * a1 * inv + 0.05f * gp4.y;
        float f2 = 0.95f * a2 * inv + 0.05f * gp4.z;
        float f3 = 0.95f * a3 * inv + 0.05f * gp4.w;
        float pf  = wsum(m * (p4.x * f0 + p4.y * f1 + p4.z * f2 + p4.w * f3));
        float pp  = wsum(m * (p4.x * p4.x + p4.y * p4.y + p4.z * p4.z + p4.w * p4.w));
        float ff  = wsum(m * (f0 * f0 + f1 * f1 + f2 * f2 + f3 * f3));
        float sfd = wsum(m * (s4.x * f0 + s4.y * f1 + s4.z * f2 + s4.w * f3));
        float ss  = wsum(m * (s4.x * s4.x + s4.y * s4.y + s4.z * s4.z + s4.w * s4.w));
        float np = fmaxf(sqrtf(pp), 1e-8f);
        float nf = fmaxf(sqrtf(ff), 1e-8f);
        float ns = fmaxf(sqrtf(ss), 1e-8f);
        float agree  = clamp01((pf  / (np * nf) + 1.f) * 0.5f);
        float sagree = clamp01((sfd / (ns * nf) + 1.f) * 0.5f);
        float sel    = clamp01(g_selb[warp] + 0.2f * sagree);
        float anchor = g_anchor[warp];
        float ug = g_rgate[warp] * sel * agree * (1.f - anchor);
        float rc = 0.15f * g_scal[3] * ug;
        float o0 = fmaxf(anchor * s4.x + (1.f - anchor) * p4.x + rc * (f0 - p4.x), 0.f);
        float o1 = fmaxf(anchor * s4.y + (1.f - anchor) * p4.y + rc * (f1 - p4.y), 0.f);
        float o2 = fmaxf(anchor * s4.z + (1.f - anchor) * p4.z + rc * (f2 - p4.z), 0.f);
        float o3 = fmaxf(anchor * s4.w + (1.f - anchor) * p4.w + rc * (f3 - p4.w), 0.f);
        int outb = (MODE == 0) ? 0 : (bufin ^ 1);
        float*   pout_f = outb ? g_propB  : g_propA;
        uint8_t* pout_q = outb ? g_propBq : g_propAq;
        if (lane < 16) {
            *reinterpret_cast<float4*>(pout_f + row + 4 * g) =
                make_float4(o0, o1, o2, o3);
            reinterpret_cast<uint32_t*>(pout_q + row)[g] =
                float4_to_fp8x4(o0, o1, o2, o3);
            if (MODE == 0)
                *reinterpret_cast<float4*>(g_bctx + row + 4 * g) =
                    make_float4(b0, b1, b2, b3);
        }
    } else {
        // MODE 3: accept & blend. a0..a3 = prop_ctx cols.
        const float* __restrict__ pin = bufin ? g_propB : g_propA;
        float4 p4  = *reinterpret_cast<const float4*>(pin + row + 4 * g);
        float4 bc4 = *reinterpret_cast<const float4*>(g_bctx + row + 4 * g);
        float sbc = wsum(m * (s4.x * bc4.x + s4.y * bc4.y + s4.z * bc4.z + s4.w * bc4.w));
        float ss  = wsum(m * (s4.x * s4.x + s4.y * s4.y + s4.z * s4.z + s4.w * s4.w));
        float bb  = wsum(m * (bc4.x * bc4.x + bc4.y * bc4.y + bc4.z * bc4.z + bc4.w * bc4.w));
        float ppc = wsum(m * (p4.x * a0 + p4.y * a1 + p4.z * a2 + p4.w * a3));
        float pp  = wsum(m * (p4.x * p4.x + p4.y * p4.y + p4.z * p4.z + p4.w * p4.w));
        float cc  = wsum(m * (a0 * a0 + a1 * a1 + a2 * a2 + a3 * a3));
        float ms  = wsum(m * (s4.x + s4.y + s4.z + s4.w));
        float mp  = wsum(m * (p4.x + p4.y + p4.z + p4.w));
        // lane-local top2 of 4, masked to -inf on dup half, then warp top2
        float sa = fmaxf(s4.x, s4.y), sb = fminf(s4.x, s4.y);
        float sc = fmaxf(s4.z, s4.w), sd = fminf(s4.z, s4.w);
        float s1 = fmaxf(sa, sc);
        float s2 = fmaxf(fminf(sa, sc), fmaxf(sb, sd));
        float pa = fmaxf(p4.x, p4.y), pb = fminf(p4.x, p4.y);
        float pc_ = fmaxf(p4.z, p4.w), pd = fminf(p4.z, p4.w);
        float p1 = fmaxf(pa, pc_);
        float p2 = fmaxf(fminf(pa, pc_), fmaxf(pb, pd));
        if (lane >= 16) { s1 = -1e30f; s2 = -1e30f; p1 = -1e30f; p2 = -1e30f; }
        wtop2(s1, s2);
        wtop2(p1, p2);
        float ns_ = fmaxf(sqrtf(ss), 1e-8f);
        float nbc = fmaxf(sqrtf(bb), 1e-8f);
        float np_ = fmaxf(sqrtf(pp), 1e-8f);
        float npc = fmaxf(sqrtf(cc), 1e-8f);
        float lqb = clamp01((sbc / (ns_ * nbc) + 1.f) * 0.5f);
        float lqp = clamp01((ppc / (np_ * npc) + 1.f) * 0.5f);
        float mb  = (s1 - s2) / (ms + 1e-8f);
        float mpg = (p1 - p2) / (mp + 1e-8f);
        // clustering term cancels in qp - qb
        float accept = sigmoidf(12.f * ((0.7f * lqp + 0.2f * mpg) -
                                        (0.7f * lqb + 0.2f * mb)));
        if (lane < 16) {
            float o0 = accept * p4.x + (1.f - accept) * s4.x;
            float o1 = accept * p4.y + (1.f - accept) * s4.y;
            float o2 = accept * p4.z + (1.f - accept) * s4.z;
            float o3 = accept * p4.w + (1.f - accept) * s4.w;
            *reinterpret_cast<float4*>(outp + row + 4 * g) =
                make_float4(o0, o1, o2, o3);
        }
    }
}

// ---------------- launch ----------------------------------------------------
extern "C" void kernel_launch(void* const* d_in, const int* in_sizes, int n_in,
                              void* d_out, int out_size) {
    (void)in_sizes; (void)n_in; (void)out_size;
    const float* logits = (const float*)d_in[0];
    const int*   esrc   = (const int*)d_in[1];
    const int*   edst   = (const int*)d_in[2];
    const float* ew     = (const float*)d_in[3];
    const float* sf     = (const float*)d_in[4];
    float* out = (float*)d_out;

    const int NODE_BLOCKS = (NN + 7) / 8;   // warp per node, 8 warps/block

    k_seed<<<NB, 256>>>(logits, sf);
    k_conf<<<NB, 256>>>(sf);
    k_hist<<<(NE + 511) / 512, 512>>>(edst);
    k_scan1<<<NCH, 1024>>>();
    k_scan2<<<1, 128>>>();
    k_scan3<<<(NN + 255) / 256, 256>>>();
    k_scat<<<(NE + 511) / 512, 512>>>(esrc, edst, ew);

    k_fused<0><<<NODE_BLOCKS, 256>>>(0, out);  // seed gather + update1 -> A
    k_fused<1><<<NODE_BLOCKS, 256>>>(0, out);  // A -> update2 -> B
    k_fused<1><<<NODE_BLOCKS, 256>>>(1, out);  // B -> update3 -> A
    k_fused<3><<<NODE_BLOCKS, 256>>>(0, out);  // prop_ctx(A) + accept -> out
}

// round 15
// speedup vs baseline: 1.1620x; 1.0031x over previous
#include <cuda_runtime.h>
#include <cuda_fp16.h>
#include <cuda_fp8.h>
#include <math.h>
#include <stdint.h>

#define NN 100000
#define NC 64
#define NE 3200000
#define NB 400          // blocks for node-elementwise kernels (256 thr)
#define NCH 98          // ceil(NN/1024) scan chunks

// ---------------- scratch (static __device__ — no allocations allowed) ------
__device__ float   g_seed  [(size_t)NN * NC];
__device__ uint8_t g_seed_q[(size_t)NN * NC];     // e4m3
__device__ float   g_propA [(size_t)NN * NC];
__device__ float   g_propB [(size_t)NN * NC];
__device__ uint8_t g_propAq[(size_t)NN * NC];     // e4m3
__device__ uint8_t g_propBq[(size_t)NN * NC];     // e4m3
__device__ float   g_bctx  [(size_t)NN * NC];
__device__ float   g_mass[NN], g_ent[NN];
__device__ float   g_sgate[NN], g_rgate[NN], g_anchor[NN], g_selb[NN], g_den[NN];
__device__ int     g_hist[NN];
__device__ int     g_off[NN + 1];
__device__ int     g_cur[NN];
__device__ int2    g_edge[NE];                    // {src, half2(w, w*sgate[src])}
__device__ int     g_csum[NCH], g_cbase[NCH];
__device__ float   g_pmass[NB], g_pclust[NB];
__device__ float   g_scal[4];                     // 2: conf_sum, 3: graph_scale
__device__ float   g_gp[NC];

// ---------------- helpers ---------------------------------------------------
__device__ __forceinline__ float wsum(float v) {
    #pragma unroll
    for (int o = 16; o; o >>= 1) v += __shfl_xor_sync(0xffffffffu, v, o);
    return v;
}
__device__ __forceinline__ void wtop2(float& m1, float& m2) {
    #pragma unroll
    for (int o = 16; o; o >>= 1) {
        float o1 = __shfl_xor_sync(0xffffffffu, m1, o);
        float o2 = __shfl_xor_sync(0xffffffffu, m2, o);
        float hi = fmaxf(m1, o1);
        float lo = fmaxf(fminf(m1, o1), fmaxf(m2, o2));
        m1 = hi; m2 = lo;
    }
}
__device__ __forceinline__ float clamp01(float x) { return fminf(fmaxf(x, 0.f), 1.f); }
__device__ __forceinline__ float sigmoidf(float x) { return 1.f / (1.f + expf(-x)); }

// 4 × e4m3 (packed u32, ch0 = low byte) -> 4 floats  (cuda_fp8.h intrinsics)
__device__ __forceinline__ float4 fp8x4_to_float4(uint32_t v) {
    __nv_fp8x2_storage_t lo = (__nv_fp8x2_storage_t)(v & 0xffffu);
    __nv_fp8x2_storage_t hi = (__nv_fp8x2_storage_t)(v >> 16);
    __half2_raw h01 = __nv_cvt_fp8x2_to_halfraw2(lo, __NV_E4M3);
    __half2_raw h23 = __nv_cvt_fp8x2_to_halfraw2(hi, __NV_E4M3);
    float2 f01 = __half22float2(*reinterpret_cast<__half2*>(&h01));
    float2 f23 = __half22float2(*reinterpret_cast<__half2*>(&h23));
    return make_float4(f01.x, f01.y, f23.x, f23.y);
}
// 4 floats -> packed 4 × e4m3 (c0 in lowest byte)
__device__ __forceinline__ uint32_t float4_to_fp8x4(float c0, float c1, float c2, float c3) {
    __nv_fp8x2_storage_t lo =
        __nv_cvt_float2_to_fp8x2(make_float2(c0, c1), __NV_SATFINITE, __NV_E4M3);
    __nv_fp8x2_storage_t hi =
        __nv_cvt_float2_to_fp8x2(make_float2(c2, c3), __NV_SATFINITE, __NV_E4M3);
    return (uint32_t)lo | ((uint32_t)hi << 16);
}
__device__ __forceinline__ unsigned short float2_to_fp8x2(float c0, float c1) {
    return (unsigned short)
        __nv_cvt_float2_to_fp8x2(make_float2(c0, c1), __NV_SATFINITE, __NV_E4M3);
}

// ---------------- kernels ---------------------------------------------------
// seed = relu(logits); mass/entropy; partial sums; zero hist/gp/scal
__global__ void __launch_bounds__(256) k_seed(const float* __restrict__ logits,
                                              const float* __restrict__ sf) {
    __shared__ float sm_mass[8], sm_clust[8];
    int t = blockIdx.x * blockDim.x + threadIdx.x;
    if (t < NN) g_hist[t] = 0;
    if (t < NC) g_gp[t] = 0.f;
    if (t < 4)  g_scal[t] = 0.f;
    int warp = t >> 5;
    int lane = threadIdx.x & 31;
    int wib  = threadIdx.x >> 5;
    int nw   = (gridDim.x * blockDim.x) >> 5;
    float lmass = 0.f, lclust = 0.f;
    for (int n = warp; n < NN; n += nw) {
        float2 lg = reinterpret_cast<const float2*>(logits + (size_t)n * NC)[lane];
        float2 s  = make_float2(fmaxf(lg.x, 0.f), fmaxf(lg.y, 0.f));
        reinterpret_cast<float2*>(g_seed + (size_t)n * NC)[lane] = s;
        reinterpret_cast<unsigned short*>(g_seed_q + (size_t)n * NC)[lane] =
            float2_to_fp8x2(s.x, s.y);
        float mass = wsum(s.x + s.y);
        float inv  = 1.f / (mass + 1e-8f);
        float nx = s.x * inv, ny = s.y * inv;
        float e   = -(nx * logf(nx + 1e-8f) + ny * logf(ny + 1e-8f));
        float ent = wsum(e);
        if (lane == 0) {
            g_mass[n] = mass; g_ent[n] = ent;
            lmass += mass; lclust += sf[2 * n + 1];
        }
    }
    if (lane == 0) { sm_mass[wib] = lmass; sm_clust[wib] = lclust; }
    __syncthreads();
    if (threadIdx.x == 0) {
        float m = 0.f, c = 0.f;
        #pragma unroll
        for (int i = 0; i < 8; i++) { m += sm_mass[i]; c += sm_clust[i]; }
        g_pmass[blockIdx.x] = m; g_pclust[blockIdx.x] = c;
    }
}

// confidence, gates, anchor, selective-base; global prior numerator & conf sum
__global__ void __launch_bounds__(256) k_conf(const float* __restrict__ sf) {
    __shared__ float sm[256];
    float acc = 0.f;
    for (int i = threadIdx.x; i < NB; i += 256) acc += g_pmass[i];
    sm[threadIdx.x] = acc;
    __syncthreads();
    for (int o = 128; o; o >>= 1) {
        if (threadIdx.x < o) sm[threadIdx.x] += sm[threadIdx.x + o];
        __syncthreads();
    }
    float scale = fmaxf(sm[0] * (1.f / (float)NN), 1e-8f);
    __syncthreads();

    int warp = (blockIdx.x * blockDim.x + threadIdx.x) >> 5;
    int lane = threadIdx.x & 31;
    int nw   = (gridDim.x * blockDim.x) >> 5;
    const float invlog = 1.f / logf(64.f);
    float2 gpacc = make_float2(0.f, 0.f);
    float lconf = 0.f;
    for (int n = warp; n < NN; n += nw) {
        float mass = g_mass[n], ent = g_ent[n];
        float cert = 1.f - ent * invlog;
        float mag  = tanhf(mass / scale);
        float conf = clamp01(0.5f * cert + 0.5f * mag);
        float2 s = reinterpret_cast<const float2*>(g_seed + (size_t)n * NC)[lane];
        gpacc.x += conf * s.x;  gpacc.y += conf * s.y;
        if (lane == 0) {
            lconf += conf;
            g_sgate[n]  = sigmoidf(8.f * (conf - 0.55f));
            g_rgate[n]  = sigmoidf(8.f * (0.5f - conf));
            g_anchor[n] = fminf(fmaxf(0.6f + 0.2f * conf, 0.f), 0.995f);
            float ld = clamp01(1.f - sf[2 * n + 0]);
            float lc = clamp01(1.f - sf[2 * n + 1]);
            g_selb[n] = (1.f - conf) + 0.25f * ld + 0.2f * lc;
        }
    }
    atomicAdd(&g_gp[2 * lane + 0], gpacc.x);
    atomicAdd(&g_gp[2 * lane + 1], gpacc.y);
    if (lane == 0) atomicAdd(&g_scal[2], lconf);
}

// histogram of dst + finalize global prior & graph_scale
__global__ void k_hist(const int* __restrict__ dst) {
    if (blockIdx.x == 0 && threadIdx.x == 0) {
        float c = 0.f;
        for (int i = 0; i < NB; i++) c += g_pclust[i];
        g_scal[3] = fminf(fmaxf(1.f - c * (1.f / (float)NN), 0.2f), 1.f);
    }
    if (blockIdx.x == 1 && threadIdx.x < NC) {
        g_gp[threadIdx.x] /= fmaxf(g_scal[2], 1e-8f);
    }
    int e = blockIdx.x * blockDim.x + threadIdx.x;
    int stride = gridDim.x * blockDim.x;
    for (; e < NE; e += stride) atomicAdd(&g_hist[dst[e]], 1);
}

// ---- parallel 3-phase exclusive scan of g_hist -> g_off, g_cur -------------
__global__ void __launch_bounds__(1024) k_scan1() {
    __shared__ int wsums[32];
    int tid = threadIdx.x;
    int lane = tid & 31;
    int i = blockIdx.x * 1024 + tid;
    int v = (i < NN) ? g_hist[i] : 0;
    int x = v;
    #pragma unroll
    for (int o = 1; o < 32; o <<= 1) {
        int t = __shfl_up_sync(0xffffffffu, x, o);
        if (lane >= o) x += t;
    }
    if (lane == 31) wsums[tid >> 5] = x;
    __syncthreads();
    if (tid < 32) {
        int s = wsums[tid];
        #pragma unroll
        for (int o = 1; o < 32; o <<= 1) {
            int t = __shfl_up_sync(0xffffffffu, s, o);
            if (lane >= o) s += t;
        }
        wsums[tid] = s;
    }
    __syncthreads();
    int base = (tid >= 32) ? wsums[(tid >> 5) - 1] : 0;
    int inc = x + base;
    if (i < NN) g_off[i] = inc - v;
    if (tid == 1023) g_csum[blockIdx.x] = inc;
}
__global__ void k_scan2() {
    __shared__ int sh[128];
    int tid = threadIdx.x;
    int v = (tid < NCH) ? g_csum[tid] : 0;
    sh[tid] = v;
    __syncthreads();
    for (int o = 1; o < 128; o <<= 1) {
        int t = (tid >= o) ? sh[tid - o] : 0;
        __syncthreads();
        sh[tid] += t;
        __syncthreads();
    }
    if (tid < NCH) g_cbase[tid] = sh[tid] - v;
}
__global__ void k_scan3() {
    int i = blockIdx.x * blockDim.x + threadIdx.x;
    if (i < NN) {
        int off = g_off[i] + g_cbase[i >> 10];
        g_off[i] = off;
        g_cur[i] = off;
    }
    if (i == 0) g_off[NN] = NE;
}

// scatter into dst-sorted 8B edge records {src, half2(w, w*sgate[src])}
__global__ void k_scat(const int* __restrict__ src, const int* __restrict__ dst,
                       const float* __restrict__ w) {
    int e = blockIdx.x * blockDim.x + threadIdx.x;
    int stride = gridDim.x * blockDim.x;
    for (; e < NE; e += stride) {
        int d = dst[e];
        int s = src[e];
        float wv = w[e];
        float sg = g_sgate[s];
        int pos = atomicAdd(&g_cur[d], 1);
        __half2 hp = __halves2half2(__float2half_rn(wv),
                                    __float2half_rn(wv * sg));
        int2 rec;
        rec.x = s;
        rec.y = *reinterpret_cast<int*>(&hp);
        g_edge[pos] = rec;
    }
}

// ---------------- fused gather-SPMM + epilogue -------------------------------
// Warp per dst node. Half-warp per edge; edge record read via broadcast LDG.
// Main loop: CHAINS independent rec->row load chains per iteration
// (CHAINS=4 for MODE 0 [heavier epilogue/regs], 8 for MODE 1/3).
// MODE 0: x=seed_q  (w2), den & bctx, update with p=seed  -> propA (+fp8)
// MODE 1: x=prop_q  (w2), update with p=prop[bufin]       -> prop[bufin^1]
// MODE 3: x=prop_q  (w),  prop_ctx + fused accept/blend   -> out
template <int MODE>
__global__ void __launch_bounds__(256) k_fused(int bufin, float* __restrict__ outp) {
    constexpr int CHAINS = (MODE == 0) ? 4 : 8;
    int warp = (blockIdx.x * blockDim.x + threadIdx.x) >> 5;
    if (warp >= NN) return;
    int lane = threadIdx.x & 31;
    int g    = lane & 15;
    int half = lane >> 4;        // 0 or 1: which edge of the pair
    const uint32_t* __restrict__ xq =
        (MODE == 0) ? reinterpret_cast<const uint32_t*>(g_seed_q)
                    : reinterpret_cast<const uint32_t*>(bufin ? g_propBq : g_propAq);
    int beg = g_off[warp], end = g_off[warp + 1];
    float a0 = 0.f, a1 = 0.f, a2 = 0.f, a3 = 0.f;
    float b0 = 0.f, b1 = 0.f, b2 = 0.f, b3 = 0.f;
    float dacc = 0.f;
    float dmask = (g == 0) ? 1.f : 0.f;   // one lane per half counts each edge

    int e = beg;
    // main loop: 2*CHAINS edges per iteration, CHAINS independent chains
    for (; e + 2 * CHAINS <= end; e += 2 * CHAINS) {
        int2 rec[CHAINS];
        #pragma unroll
        for (int c = 0; c < CHAINS; c++)
            rec[c] = __ldg(&g_edge[e + 2 * c + half]);
        uint32_t v[CHAINS];
        #pragma unroll
        for (int c = 0; c < CHAINS; c++)
            v[c] = __ldg(&xq[(size_t)rec[c].x * 16 + g]);
        #pragma unroll
        for (int c = 0; c < CHAINS; c++) {
            __half2 wp = *reinterpret_cast<__half2*>(&rec[c].y);
            float w  = __low2float(wp);
            float w2 = __high2float(wp);
            float4 f = fp8x4_to_float4(v[c]);
            float wa = (MODE == 3) ? w : w2;
            a0 = fmaf(wa, f.x, a0); a1 = fmaf(wa, f.y, a1);
            a2 = fmaf(wa, f.z, a2); a3 = fmaf(wa, f.w, a3);
            if (MODE == 0) {
                dacc += dmask * w2;
                b0 = fmaf(w, f.x, b0); b1 = fmaf(w, f.y, b1);
                b2 = fmaf(w, f.z, b2); b3 = fmaf(w, f.w, b3);
            }
        }
    }
    // tail: processed in masked pairs
    for (; e < end; e += 2) {
        int idx = e + half;
        bool valid = idx < end;
        int2 rec = __ldg(&g_edge[valid ? idx : beg]);
        __half2 wp = *reinterpret_cast<__half2*>(&rec.y);
        float w  = valid ? __low2float(wp)  : 0.f;
        float w2 = valid ? __high2float(wp) : 0.f;
        uint32_t v = __ldg(&xq[(size_t)rec.x * 16 + g]);
        float4 f = fp8x4_to_float4(v);
        float wa = (MODE == 3) ? w : w2;
        a0 = fmaf(wa, f.x, a0); a1 = fmaf(wa, f.y, a1);
        a2 = fmaf(wa, f.z, a2); a3 = fmaf(wa, f.w, a3);
        if (MODE == 0) {
            dacc += dmask * w2;
            b0 = fmaf(w, f.x, b0); b1 = fmaf(w, f.y, b1);
            b2 = fmaf(w, f.z, b2); b3 = fmaf(w, f.w, b3);
        }
    }

    a0 += __shfl_xor_sync(0xffffffffu, a0, 16);
    a1 += __shfl_xor_sync(0xffffffffu, a1, 16);
    a2 += __shfl_xor_sync(0xffffffffu, a2, 16);
    a3 += __shfl_xor_sync(0xffffffffu, a3, 16);
    if (MODE == 0) {
        b0 += __shfl_xor_sync(0xffffffffu, b0, 16);
        b1 += __shfl_xor_sync(0xffffffffu, b1, 16);
        b2 += __shfl_xor_sync(0xffffffffu, b2, 16);
        b3 += __shfl_xor_sync(0xffffffffu, b3, 16);
    }
    size_t row = (size_t)warp * NC;
    float4 s4 = *reinterpret_cast<const float4*>(g_seed + row + 4 * g);
    float m = (lane < 16) ? 1.f : 0.f;   // kill duplicate half in reductions

    if (MODE == 0 || MODE == 1) {
        float den;
        if (MODE == 0) {
            den = wsum(dacc);
            if (lane == 0) g_den[warp] = den;
        } else {
            den = g_den[warp];
        }
        const float* __restrict__ pin =
            (MODE == 0) ? g_seed : (bufin ? g_propB : g_propA);
        float4 p4 = (MODE == 0) ? s4
                  : *reinterpret_cast<const float4*>(pin + row + 4 * g);
        float4 gp4 = reinterpret_cast<const float4*>(g_gp)[g];
        float inv = 1.f / fmaxf(den, 1e-8f);
        float f0 = 0.95f * a0 * inv + 0.05f * gp4.x;
        float f1 = 0.95f * a1 * inv + 0.05f * gp4.y;
        float f2 = 0.95f * a2 * inv + 0.05f * gp4.z;
        float f3 = 0.95f * a3 * inv + 0.05f * gp4.w;
        float pf  = wsum(m * (p4.x * f0 + p4.y * f1 + p4.z * f2 + p4.w * f3));
        float pp  = wsum(m * (p4.x * p4.x + p4.y * p4.y + p4.z * p4.z + p4.w * p4.w));
        float ff  = wsum(m * (f0 * f0 + f1 * f1 + f2 * f2 + f3 * f3));
        float sfd = wsum(m * (s4.x * f0 + s4.y * f1 + s4.z * f2 + s4.w * f3));
        float ss  = wsum(m * (s4.x * s4.x + s4.y * s4.y + s4.z * s4.z + s4.w * s4.w));
        float np = fmaxf(sqrtf(pp), 1e-8f);
        float nf = fmaxf(sqrtf(ff), 1e-8f);
        float ns = fmaxf(sqrtf(ss), 1e-8f);
        float agree  = clamp01((pf  / (np * nf) + 1.f) * 0.5f);
        float sagree = clamp01((sfd / (ns * nf) + 1.f) * 0.5f);
        float sel    = clamp01(g_selb[warp] + 0.2f * sagree);
        float anchor = g_anchor[warp];
        float ug = g_rgate[warp] * sel * agree * (1.f - anchor);
        float rc = 0.15f * g_scal[3] * ug;
        float o0 = fmaxf(anchor * s4.x + (1.f - anchor) * p4.x + rc * (f0 - p4.x), 0.f);
        float o1 = fmaxf(anchor * s4.y + (1.f - anchor) * p4.y + rc * (f1 - p4.y), 0.f);
        float o2 = fmaxf(anchor * s4.z + (1.f - anchor) * p4.z + rc * (f2 - p4.z), 0.f);
        float o3 = fmaxf(anchor * s4.w + (1.f - anchor) * p4.w + rc * (f3 - p4.w), 0.f);
        int outb = (MODE == 0) ? 0 : (bufin ^ 1);
        float*   pout_f = outb ? g_propB  : g_propA;
        uint8_t* pout_q = outb ? g_propBq : g_propAq;
        if (lane < 16) {
            *reinterpret_cast<float4*>(pout_f + row + 4 * g) =
                make_float4(o0, o1, o2, o3);
            reinterpret_cast<uint32_t*>(pout_q + row)[g] =
                float4_to_fp8x4(o0, o1, o2, o3);
            if (MODE == 0)
                *reinterpret_cast<float4*>(g_bctx + row + 4 * g) =
                    make_float4(b0, b1, b2, b3);
        }
    } else {
        // MODE 3: accept & blend. a0..a3 = prop_ctx cols.
        const float* __restrict__ pin = bufin ? g_propB : g_propA;
        float4 p4  = *reinterpret_cast<const float4*>(pin + row + 4 * g);
        float4 bc4 = *reinterpret_cast<const float4*>(g_bctx + row + 4 * g);
        float sbc = wsum(m * (s4.x * bc4.x + s4.y * bc4.y + s4.z * bc4.z + s4.w * bc4.w));
        float ss  = wsum(m * (s4.x * s4.x + s4.y * s4.y + s4.z * s4.z + s4.w * s4.w));
        float bb  = wsum(m * (bc4.x * bc4.x + bc4.y * bc4.y + bc4.z * bc4.z + bc4.w * bc4.w));
        float ppc = wsum(m * (p4.x * a0 + p4.y * a1 + p4.z * a2 + p4.w * a3));
        float pp  = wsum(m * (p4.x * p4.x + p4.y * p4.y + p4.z * p4.z + p4.w * p4.w));
        float cc  = wsum(m * (a0 * a0 + a1 * a1 + a2 * a2 + a3 * a3));
        float ms  = wsum(m * (s4.x + s4.y + s4.z + s4.w));
        float mp  = wsum(m * (p4.x + p4.y + p4.z + p4.w));
        // lane-local top2 of 4, masked to -inf on dup half, then warp top2
        float sa = fmaxf(s4.x, s4.y), sb = fminf(s4.x, s4.y);
        float sc = fmaxf(s4.z, s4.w), sd = fminf(s4.z, s4.w);
        float s1 = fmaxf(sa, sc);
        float s2 = fmaxf(fminf(sa, sc), fmaxf(sb, sd));
        float pa = fmaxf(p4.x, p4.y), pb = fminf(p4.x, p4.y);
        float pc_ = fmaxf(p4.z, p4.w), pd = fminf(p4.z, p4.w);
        float p1 = fmaxf(pa, pc_);
        float p2 = fmaxf(fminf(pa, pc_), fmaxf(pb, pd));
        if (lane >= 16) { s1 = -1e30f; s2 = -1e30f; p1 = -1e30f; p2 = -1e30f; }
        wtop2(s1, s2);
        wtop2(p1, p2);
        float ns_ = fmaxf(sqrtf(ss), 1e-8f);
        float nbc = fmaxf(sqrtf(bb), 1e-8f);
        float np_ = fmaxf(sqrtf(pp), 1e-8f);
        float npc = fmaxf(sqrtf(cc), 1e-8f);
        float lqb = clamp01((sbc / (ns_ * nbc) + 1.f) * 0.5f);
        float lqp = clamp01((ppc / (np_ * npc) + 1.f) * 0.5f);
        float mb  = (s1 - s2) / (ms + 1e-8f);
        float mpg = (p1 - p2) / (mp + 1e-8f);
        // clustering term cancels in qp - qb
        float accept = sigmoidf(12.f * ((0.7f * lqp + 0.2f * mpg) -
                                        (0.7f * lqb + 0.2f * mb)));
        if (lane < 16) {
            float o0 = accept * p4.x + (1.f - accept) * s4.x;
            float o1 = accept * p4.y + (1.f - accept) * s4.y;
            float o2 = accept * p4.z + (1.f - accept) * s4.z;
            float o3 = accept * p4.w + (1.f - accept) * s4.w;
            *reinterpret_cast<float4*>(outp + row + 4 * g) =
                make_float4(o0, o1, o2, o3);
        }
    }
}

// ---------------- launch ----------------------------------------------------
extern "C" void kernel_launch(void* const* d_in, const int* in_sizes, int n_in,
                              void* d_out, int out_size) {
    (void)in_sizes; (void)n_in; (void)out_size;
    const float* logits = (const float*)d_in[0];
    const int*   esrc   = (const int*)d_in[1];
    const int*   edst   = (const int*)d_in[2];
    const float* ew     = (const float*)d_in[3];
    const float* sf     = (const float*)d_in[4];
    float* out = (float*)d_out;

    const int NODE_BLOCKS = (NN + 7) / 8;   // warp per node, 8 warps/block

    k_seed<<<NB, 256>>>(logits, sf);
    k_conf<<<NB, 256>>>(sf);
    k_hist<<<(NE + 511) / 512, 512>>>(edst);
    k_scan1<<<NCH, 1024>>>();
    k_scan2<<<1, 128>>>();
    k_scan3<<<(NN + 255) / 256, 256>>>();
    k_scat<<<(NE + 511) / 512, 512>>>(esrc, edst, ew);

    k_fused<0><<<NODE_BLOCKS, 256>>>(0, out);  // seed gather + update1 -> A
    k_fused<1><<<NODE_BLOCKS, 256>>>(0, out);  // A -> update2 -> B
    k_fused<1><<<NODE_BLOCKS, 256>>>(1, out);  // B -> update3 -> A
    k_fused<3><<<NODE_BLOCKS, 256>>>(0, out);  // prop_ctx(A) + accept -> out
}